// round 4
// baseline (speedup 1.0000x reference)
#include <cuda_runtime.h>
#include <cstddef>

#define NAPP 100000
#define NATTR 50000
#define NEDGE 500000
#define D 128

// ---------------- scratch (device globals; no allocation allowed) ----------------
__device__ __align__(256) float g_s0[NATTR * D];
__device__ __align__(256) float g_s1[NAPP * D];
__device__ __align__(256) float g_s2[NAPP * D];
__device__ __align__(256) float g_s1b[NAPP * D];
__device__ __align__(256) float g_s2b[NAPP * D];
__device__ __align__(256) float g_deg0[NATTR];
__device__ __align__(256) float g_deg1[NAPP];
__device__ __align__(256) float g_deg2[NAPP];
__device__ __align__(256) float g_inv0[NATTR];
__device__ __align__(256) float g_inv1[NAPP];
__device__ __align__(256) float g_inv2[NAPP];
__device__ __align__(256) float g_hattr[NATTR * D];
__device__ __align__(256) float g_happ[NAPP * D];
__device__ __align__(256) float g_WappSelf[D * D];
__device__ __align__(256) float g_bapp[D];
__device__ __align__(256) float g_Wsc[D * 2];
__device__ __align__(256) float g_Wn1c[D * 2];
__device__ __align__(256) float g_Wn2c[D * 2];
__device__ __align__(256) float g_bc2[2];

// ---------------- zero scratch accumulators ----------------
__global__ void zero_kernel() {
    size_t stride = (size_t)gridDim.x * blockDim.x;
    size_t gt = (size_t)blockIdx.x * blockDim.x + threadIdx.x;
    float4 z = make_float4(0.f, 0.f, 0.f, 0.f);
    for (size_t i = gt; i < (size_t)NATTR * D / 4; i += stride) ((float4*)g_s0)[i] = z;
    for (size_t i = gt; i < (size_t)NAPP * D / 4; i += stride) {
        ((float4*)g_s1)[i] = z;
        ((float4*)g_s2)[i] = z;
        ((float4*)g_s1b)[i] = z;
        ((float4*)g_s2b)[i] = z;
    }
    for (size_t i = gt; i < NAPP; i += stride) {
        g_deg1[i] = 0.f; g_deg2[i] = 0.f;
        if (i < NATTR) g_deg0[i] = 0.f;
    }
}

// ---------------- fold weights: Wself1[1]+Wself1[2], b1[1]+b1[2], and layer2@Wc ----------------
__global__ void prep_kernel(const float* __restrict__ Wself1, const float* __restrict__ b1,
                            const float* __restrict__ Wself2, const float* __restrict__ Wneigh2,
                            const float* __restrict__ b2, const float* __restrict__ Wc,
                            const float* __restrict__ bc) {
    int t = threadIdx.x;
    for (int idx = t; idx < D * D; idx += 256)
        g_WappSelf[idx] = Wself1[D * D + idx] + Wself1[2 * D * D + idx];
    if (t < D) g_bapp[t] = b1[D + t] + b1[2 * D + t];
    {
        int k = t >> 1, o = t & 1;
        float sWs = 0.f, sW1 = 0.f, sW2 = 0.f;
        for (int j = 0; j < D; j++) {
            float wc = Wc[j * 2 + o];
            sWs += (Wself2[D * D + k * D + j] + Wself2[2 * D * D + k * D + j]) * wc;
            sW1 += Wneigh2[D * D + k * D + j] * wc;
            sW2 += Wneigh2[2 * D * D + k * D + j] * wc;
        }
        g_Wsc[k * 2 + o] = sWs;
        g_Wn1c[k * 2 + o] = sW1;
        g_Wn2c[k * 2 + o] = sW2;
    }
    if (t < 2) {
        float s = bc[t];
        for (int j = 0; j < D; j++) s += (b2[D + j] + b2[2 * D + j]) * Wc[j * 2 + t];
        g_bc2[t] = s;
    }
}

// ---------------- edge scatter: s[dst] += ew * hsrc[src]; deg[dst] += 1 ----------------
__global__ __launch_bounds__(256) void scatter_kernel(
    const float* __restrict__ hsrc, const int* __restrict__ src,
    const int* __restrict__ dst, const float* __restrict__ ew,
    float* __restrict__ s, float* __restrict__ deg) {
    int gt = blockIdx.x * 256 + threadIdx.x;
    int e = gt >> 5;
    if (e >= NEDGE) return;
    int lane = gt & 31;
    int sR = __ldg(src + e);
    int dR = __ldg(dst + e);
    float w = __ldg(ew + e);
    float4 v = __ldg((const float4*)(hsrc + (size_t)sR * D) + lane);
    v.x *= w; v.y *= w; v.z *= w; v.w *= w;
    float* p = s + (size_t)dR * D + lane * 4;
    asm volatile("red.global.add.v4.f32 [%0], {%1,%2,%3,%4};"
                 :: "l"(p), "f"(v.x), "f"(v.y), "f"(v.z), "f"(v.w) : "memory");
    if (deg != nullptr && lane == 0) atomicAdd(deg + dR, 1.0f);
}

// ---------------- inv degree ----------------
__global__ void invdeg_kernel() {
    int i = blockIdx.x * 256 + threadIdx.x;
    if (i < NAPP) {
        g_inv1[i] = 1.0f / fmaxf(g_deg1[i], 1.0f);
        g_inv2[i] = 1.0f / fmaxf(g_deg2[i], 1.0f);
        if (i < NATTR) g_inv0[i] = 1.0f / fmaxf(g_deg0[i], 1.0f);
    }
}

// ---------------- packed-f32x2 helpers ----------------
__device__ __forceinline__ unsigned long long dup_f32(float x) {
    unsigned long long r;
    asm("mov.b64 %0, {%1, %1};" : "=l"(r) : "f"(x));
    return r;
}
__device__ __forceinline__ void ffma2(unsigned long long& d, unsigned long long a,
                                      unsigned long long b) {
    asm("fma.rn.f32x2 %0, %1, %2, %0;" : "+l"(d) : "l"(a), "l"(b));
}
__device__ __forceinline__ void unpack2(unsigned long long p, float& lo, float& hi) {
    asm("mov.b64 {%0, %1}, %2;" : "=f"(lo), "=f"(hi) : "l"(p));
}

// ---------------- C = relu( sum_j (A_j * rowscale_j) @ W_j + bias ), K_j = 128 each ----
// 128x128 tile, 256 threads, 8x8 per thread, FFMA2 (fma.rn.f32x2) inner loop.
__global__ __launch_bounds__(256, 2) void gemm_relu_kernel(
    const float* __restrict__ A0, const float* __restrict__ I0,
    const float* __restrict__ A1, const float* __restrict__ I1,
    const float* __restrict__ A2, const float* __restrict__ I2,
    const float* __restrict__ W0, const float* __restrict__ W1, const float* __restrict__ W2,
    const float* __restrict__ bias, float* __restrict__ C, int M, int nin) {
    __shared__ float As[32][132];  // [k][row]
    __shared__ float Bs[32][132];  // [k][col]
    const int t = threadIdx.x;
    const int row0 = blockIdx.x * 128;
    const int trow = t >> 4;  // 0..15 -> 8 rows each
    const int tcol = t & 15;  // 0..15 -> 8 cols (4 packed pairs) each

    unsigned long long acc[8][4];
    const unsigned long long zero2 = 0ull;
#pragma unroll
    for (int i = 0; i < 8; i++)
#pragma unroll
        for (int j = 0; j < 4; j++) acc[i][j] = zero2;

    const float* Aj[3] = {A0, A1, A2};
    const float* Ij[3] = {I0, I1, I2};
    const float* Wj[3] = {W0, W1, W2};

    for (int jj = 0; jj < nin; jj++) {
        const float* A = Aj[jj];
        const float* I = Ij[jj];
        const float* W = Wj[jj];
        for (int kc = 0; kc < 4; kc++) {
            const int k0 = kc * 32;
            __syncthreads();
            // A tile: 128 rows x 32 k. f = i*256+t -> fully coalesced 128B lines.
#pragma unroll
            for (int i = 0; i < 4; i++) {
                int f = i * 256 + t;
                int r = f >> 3;
                int kq = f & 7;
                int grow = row0 + r;
                float4 v = make_float4(0.f, 0.f, 0.f, 0.f);
                if (grow < M) {
                    v = *(const float4*)(A + (size_t)grow * 128 + k0 + kq * 4);
                    if (I) { float sc = I[grow]; v.x *= sc; v.y *= sc; v.z *= sc; v.w *= sc; }
                }
                As[kq * 4 + 0][r] = v.x;
                As[kq * 4 + 1][r] = v.y;
                As[kq * 4 + 2][r] = v.z;
                As[kq * 4 + 3][r] = v.w;
            }
            // W tile: 32 k x 128 cols
#pragma unroll
            for (int i = 0; i < 4; i++) {
                int f = i * 256 + t;
                int kk = f >> 5;
                int cq = f & 31;
                *(float4*)&Bs[kk][cq * 4] =
                    *(const float4*)(W + (size_t)(k0 + kk) * 128 + cq * 4);
            }
            __syncthreads();
#pragma unroll
            for (int kk = 0; kk < 32; kk++) {
                float4 a0 = *(const float4*)&As[kk][trow * 8];
                float4 a1 = *(const float4*)&As[kk][trow * 8 + 4];
                // b pairs come straight out of LDS.128 as packed 64-bit
                ulonglong2 bq0 = *(const ulonglong2*)&Bs[kk][tcol * 8];
                ulonglong2 bq1 = *(const ulonglong2*)&Bs[kk][tcol * 8 + 4];
                unsigned long long bp[4] = {bq0.x, bq0.y, bq1.x, bq1.y};
                unsigned long long ap[8];
                ap[0] = dup_f32(a0.x); ap[1] = dup_f32(a0.y);
                ap[2] = dup_f32(a0.z); ap[3] = dup_f32(a0.w);
                ap[4] = dup_f32(a1.x); ap[5] = dup_f32(a1.y);
                ap[6] = dup_f32(a1.z); ap[7] = dup_f32(a1.w);
#pragma unroll
                for (int i = 0; i < 8; i++)
#pragma unroll
                    for (int j = 0; j < 4; j++) ffma2(acc[i][j], ap[i], bp[j]);
            }
        }
    }
    // epilogue: bias + relu + store
    int col = tcol * 8;
    float4 bA = *(const float4*)(bias + col);
    float4 bB = *(const float4*)(bias + col + 4);
    float bb[8] = {bA.x, bA.y, bA.z, bA.w, bB.x, bB.y, bB.z, bB.w};
#pragma unroll
    for (int i = 0; i < 8; i++) {
        int grow = row0 + trow * 8 + i;
        if (grow < M) {
            float o[8];
#pragma unroll
            for (int j = 0; j < 4; j++) {
                float lo, hi;
                unpack2(acc[i][j], lo, hi);
                o[2 * j] = fmaxf(lo + bb[2 * j], 0.f);
                o[2 * j + 1] = fmaxf(hi + bb[2 * j + 1], 0.f);
            }
            *(float4*)(C + (size_t)grow * 128 + col) = make_float4(o[0], o[1], o[2], o[3]);
            *(float4*)(C + (size_t)grow * 128 + col + 4) = make_float4(o[4], o[5], o[6], o[7]);
        }
    }
}

// ---------------- fused layer2 + classifier: out[i] = happ@Wsc + n1'@Wn1c + n2'@Wn2c + bc2 ----------------
__global__ __launch_bounds__(256) void final_kernel(float* __restrict__ out) {
    int gt = blockIdx.x * 256 + threadIdx.x;
    int i = gt >> 5;
    if (i >= NAPP) return;
    int lane = gt & 31;
    float4 h = ((const float4*)(g_happ + (size_t)i * D))[lane];
    float4 n1 = ((const float4*)(g_s1b + (size_t)i * D))[lane];
    float4 n2 = ((const float4*)(g_s2b + (size_t)i * D))[lane];
    float i1 = g_inv1[i], i2 = g_inv2[i];
    n1.x *= i1; n1.y *= i1; n1.z *= i1; n1.w *= i1;
    n2.x *= i2; n2.y *= i2; n2.z *= i2; n2.w *= i2;
    float hv[4] = {h.x, h.y, h.z, h.w};
    float n1v[4] = {n1.x, n1.y, n1.z, n1.w};
    float n2v[4] = {n2.x, n2.y, n2.z, n2.w};
    int k = lane * 4;
    float a0 = 0.f, a1 = 0.f;
#pragma unroll
    for (int c = 0; c < 4; c++) {
        a0 += hv[c] * g_Wsc[(k + c) * 2 + 0] + n1v[c] * g_Wn1c[(k + c) * 2 + 0] +
              n2v[c] * g_Wn2c[(k + c) * 2 + 0];
        a1 += hv[c] * g_Wsc[(k + c) * 2 + 1] + n1v[c] * g_Wn1c[(k + c) * 2 + 1] +
              n2v[c] * g_Wn2c[(k + c) * 2 + 1];
    }
#pragma unroll
    for (int off = 16; off; off >>= 1) {
        a0 += __shfl_down_sync(0xffffffffu, a0, off);
        a1 += __shfl_down_sync(0xffffffffu, a1, off);
    }
    if (lane == 0) {
        out[2 * i + 0] = a0 + g_bc2[0];
        out[2 * i + 1] = a1 + g_bc2[1];
    }
}

extern "C" void kernel_launch(void* const* d_in, const int* in_sizes, int n_in,
                              void* d_out, int out_size) {
    const float* x_app = (const float*)d_in[0];
    const float* x_attr = (const float*)d_in[1];
    const float* ew0 = (const float*)d_in[2];
    const float* ew1 = (const float*)d_in[3];
    const float* ew2 = (const float*)d_in[4];
    const float* Wself1 = (const float*)d_in[5];
    const float* Wneigh1 = (const float*)d_in[6];
    const float* b1 = (const float*)d_in[7];
    const float* Wself2 = (const float*)d_in[8];
    const float* Wneigh2 = (const float*)d_in[9];
    const float* b2 = (const float*)d_in[10];
    const float* Wc = (const float*)d_in[11];
    const float* bc = (const float*)d_in[12];
    const int* src0 = (const int*)d_in[13];
    const int* dst0 = (const int*)d_in[14];
    const int* src1 = (const int*)d_in[15];
    const int* dst1 = (const int*)d_in[16];
    const int* src2 = (const int*)d_in[17];
    const int* dst2 = (const int*)d_in[18];
    float* out = (float*)d_out;

    float *s0, *s1, *s2, *s1b, *s2b, *deg0, *deg1, *deg2;
    float *inv0, *inv1, *inv2, *hattr, *happ, *WappSelf, *bapp;
    cudaGetSymbolAddress((void**)&s0, g_s0);
    cudaGetSymbolAddress((void**)&s1, g_s1);
    cudaGetSymbolAddress((void**)&s2, g_s2);
    cudaGetSymbolAddress((void**)&s1b, g_s1b);
    cudaGetSymbolAddress((void**)&s2b, g_s2b);
    cudaGetSymbolAddress((void**)&deg0, g_deg0);
    cudaGetSymbolAddress((void**)&deg1, g_deg1);
    cudaGetSymbolAddress((void**)&deg2, g_deg2);
    cudaGetSymbolAddress((void**)&inv0, g_inv0);
    cudaGetSymbolAddress((void**)&inv1, g_inv1);
    cudaGetSymbolAddress((void**)&inv2, g_inv2);
    cudaGetSymbolAddress((void**)&hattr, g_hattr);
    cudaGetSymbolAddress((void**)&happ, g_happ);
    cudaGetSymbolAddress((void**)&WappSelf, g_WappSelf);
    cudaGetSymbolAddress((void**)&bapp, g_bapp);

    zero_kernel<<<2048, 256>>>();
    prep_kernel<<<1, 256>>>(Wself1, b1, Wself2, Wneigh2, b2, Wc, bc);

    const int SCATTER_BLOCKS = (NEDGE * 32) / 256;  // 62500
    // layer 1 aggregations
    scatter_kernel<<<SCATTER_BLOCKS, 256>>>(x_app, src0, dst0, ew0, s0, deg0);
    scatter_kernel<<<SCATTER_BLOCKS, 256>>>(x_attr, src1, dst1, ew1, s1, deg1);
    scatter_kernel<<<SCATTER_BLOCKS, 256>>>(x_app, src2, dst2, ew2, s2, deg2);
    invdeg_kernel<<<(NAPP + 255) / 256, 256>>>();

    // layer 1 dense (128-row tiles)
    gemm_relu_kernel<<<(NATTR + 127) / 128, 256>>>(
        x_attr, nullptr, s0, inv0, nullptr, nullptr,
        Wself1, Wneigh1, nullptr, b1, hattr, NATTR, 2);
    gemm_relu_kernel<<<(NAPP + 127) / 128, 256>>>(
        x_app, nullptr, s1, inv1, s2, inv2,
        WappSelf, Wneigh1 + D * D, Wneigh1 + 2 * D * D, bapp, happ, NAPP, 3);

    // layer 2 aggregations (attr output of layer 2 is unused -> skipped)
    scatter_kernel<<<SCATTER_BLOCKS, 256>>>(hattr, src1, dst1, ew1, s1b, nullptr);
    scatter_kernel<<<SCATTER_BLOCKS, 256>>>(happ, src2, dst2, ew2, s2b, nullptr);

    // layer 2 + classifier fused (weights pre-folded through Wc)
    final_kernel<<<(NAPP * 32 + 255) / 256, 256>>>(out);
}

// round 8
// speedup vs baseline: 1.2688x; 1.2688x over previous
#include <cuda_runtime.h>
#include <cstddef>

#define NAPP 100000
#define NATTR 50000
#define NEDGE 500000
#define D 128

// ---------------- scratch (device globals; no allocation allowed) ----------------
__device__ __align__(256) float g_s0[NATTR * D];
__device__ __align__(256) float g_s1[NAPP * D];
__device__ __align__(256) float g_s2[NAPP * D];
__device__ __align__(256) float g_s1b[NAPP * D];
__device__ __align__(256) float g_s2b[NAPP * D];
__device__ __align__(256) float g_deg0[NATTR];
__device__ __align__(256) float g_deg1[NAPP];
__device__ __align__(256) float g_deg2[NAPP];
__device__ __align__(256) float g_inv0[NATTR];
__device__ __align__(256) float g_inv1[NAPP];
__device__ __align__(256) float g_inv2[NAPP];
__device__ __align__(256) float g_hattr[NATTR * D];
__device__ __align__(256) float g_happ[NAPP * D];
__device__ __align__(256) float g_WappSelf[D * D];
__device__ __align__(256) float g_bapp[D];
__device__ __align__(256) float g_Wsc[D * 2];
__device__ __align__(256) float g_Wn1c[D * 2];
__device__ __align__(256) float g_Wn2c[D * 2];
__device__ __align__(256) float g_bc2[2];

// ---------------- zero scratch accumulators ----------------
__global__ void zero_kernel() {
    size_t stride = (size_t)gridDim.x * blockDim.x;
    size_t gt = (size_t)blockIdx.x * blockDim.x + threadIdx.x;
    float4 z = make_float4(0.f, 0.f, 0.f, 0.f);
    for (size_t i = gt; i < (size_t)NATTR * D / 4; i += stride) ((float4*)g_s0)[i] = z;
    for (size_t i = gt; i < (size_t)NAPP * D / 4; i += stride) {
        ((float4*)g_s1)[i] = z;
        ((float4*)g_s2)[i] = z;
        ((float4*)g_s1b)[i] = z;
        ((float4*)g_s2b)[i] = z;
    }
    for (size_t i = gt; i < NAPP; i += stride) {
        g_deg1[i] = 0.f; g_deg2[i] = 0.f;
        if (i < NATTR) g_deg0[i] = 0.f;
    }
}

// ---------------- fold weights: Wself1[1]+Wself1[2], b1[1]+b1[2], and layer2@Wc ----------------
__global__ void prep_kernel(const float* __restrict__ Wself1, const float* __restrict__ b1,
                            const float* __restrict__ Wself2, const float* __restrict__ Wneigh2,
                            const float* __restrict__ b2, const float* __restrict__ Wc,
                            const float* __restrict__ bc) {
    int t = threadIdx.x;
    for (int idx = t; idx < D * D; idx += 256)
        g_WappSelf[idx] = Wself1[D * D + idx] + Wself1[2 * D * D + idx];
    if (t < D) g_bapp[t] = b1[D + t] + b1[2 * D + t];
    {
        int k = t >> 1, o = t & 1;
        float sWs = 0.f, sW1 = 0.f, sW2 = 0.f;
        for (int j = 0; j < D; j++) {
            float wc = Wc[j * 2 + o];
            sWs += (Wself2[D * D + k * D + j] + Wself2[2 * D * D + k * D + j]) * wc;
            sW1 += Wneigh2[D * D + k * D + j] * wc;
            sW2 += Wneigh2[2 * D * D + k * D + j] * wc;
        }
        g_Wsc[k * 2 + o] = sWs;
        g_Wn1c[k * 2 + o] = sW1;
        g_Wn2c[k * 2 + o] = sW2;
    }
    if (t < 2) {
        float s = bc[t];
        for (int j = 0; j < D; j++) s += (b2[D + j] + b2[2 * D + j]) * Wc[j * 2 + t];
        g_bc2[t] = s;
    }
}

// ---------------- edge scatter: s[dst] += ew * hsrc[src]; deg[dst] += 1 ----------------
__global__ __launch_bounds__(256) void scatter_kernel(
    const float* __restrict__ hsrc, const int* __restrict__ src,
    const int* __restrict__ dst, const float* __restrict__ ew,
    float* __restrict__ s, float* __restrict__ deg) {
    int gt = blockIdx.x * 256 + threadIdx.x;
    int e = gt >> 5;
    if (e >= NEDGE) return;
    int lane = gt & 31;
    int sR = __ldg(src + e);
    int dR = __ldg(dst + e);
    float w = __ldg(ew + e);
    float4 v = __ldg((const float4*)(hsrc + (size_t)sR * D) + lane);
    v.x *= w; v.y *= w; v.z *= w; v.w *= w;
    float* p = s + (size_t)dR * D + lane * 4;
    asm volatile("red.global.add.v4.f32 [%0], {%1,%2,%3,%4};"
                 :: "l"(p), "f"(v.x), "f"(v.y), "f"(v.z), "f"(v.w) : "memory");
    if (deg != nullptr && lane == 0) atomicAdd(deg + dR, 1.0f);
}

// ---------------- inv degree ----------------
__global__ void invdeg_kernel() {
    int i = blockIdx.x * 256 + threadIdx.x;
    if (i < NAPP) {
        g_inv1[i] = 1.0f / fmaxf(g_deg1[i], 1.0f);
        g_inv2[i] = 1.0f / fmaxf(g_deg2[i], 1.0f);
        if (i < NATTR) g_inv0[i] = 1.0f / fmaxf(g_deg0[i], 1.0f);
    }
}

// ---------------- packed-f32x2 helpers ----------------
__device__ __forceinline__ unsigned long long dup_f32(float x) {
    unsigned long long r;
    asm("mov.b64 %0, {%1, %1};" : "=l"(r) : "f"(x));
    return r;
}
__device__ __forceinline__ void ffma2(unsigned long long& d, unsigned long long a,
                                      unsigned long long b) {
    asm("fma.rn.f32x2 %0, %1, %2, %0;" : "+l"(d) : "l"(a), "l"(b));
}
__device__ __forceinline__ void unpack2(unsigned long long p, float& lo, float& hi) {
    asm("mov.b64 {%0, %1}, %2;" : "=f"(lo), "=f"(hi) : "l"(p));
}

// ---------------- C = relu( sum_j (A_j * rowscale_j) @ W_j + bias ), K_j = 128 each ----
// 64x128 tile (R2-proven geometry), 256 threads, 4 rows x 8 cols per thread,
// FFMA2 (fma.rn.f32x2) inner loop: 16 FFMA2 per k instead of 32 FFMA.
// Register budget: acc 16 pairs (32) + A dups 4 pairs (8) + B 4 pairs (8) ~= 80 regs.
__global__ __launch_bounds__(256, 2) void gemm_relu_kernel(
    const float* __restrict__ A0, const float* __restrict__ I0,
    const float* __restrict__ A1, const float* __restrict__ I1,
    const float* __restrict__ A2, const float* __restrict__ I2,
    const float* __restrict__ W0, const float* __restrict__ W1, const float* __restrict__ W2,
    const float* __restrict__ bias, float* __restrict__ C, int M, int nin) {
    __shared__ float As[32][68];   // [k][row]
    __shared__ float Bs[32][132];  // [k][col]
    const int t = threadIdx.x;
    const int row0 = blockIdx.x * 64;
    const int trow = t >> 4;  // 0..15 -> 4 rows each
    const int tcol = t & 15;  // 0..15 -> 8 cols = 4 packed pairs each

    unsigned long long acc[4][4];
#pragma unroll
    for (int i = 0; i < 4; i++)
#pragma unroll
        for (int j = 0; j < 4; j++) acc[i][j] = 0ull;

    const float* Aj[3] = {A0, A1, A2};
    const float* Ij[3] = {I0, I1, I2};
    const float* Wj[3] = {W0, W1, W2};

    for (int jj = 0; jj < nin; jj++) {
        const float* A = Aj[jj];
        const float* I = Ij[jj];
        const float* W = Wj[jj];
        for (int kc = 0; kc < 4; kc++) {
            const int k0 = kc * 32;
            __syncthreads();
            // A tile: 64 rows x 32 k (512 float4 loads, transposed store)
#pragma unroll
            for (int i = 0; i < 2; i++) {
                int f = t * 2 + i;
                int r = f >> 3;
                int kq = f & 7;
                int grow = row0 + r;
                float4 v = make_float4(0.f, 0.f, 0.f, 0.f);
                if (grow < M) {
                    v = *(const float4*)(A + (size_t)grow * 128 + k0 + kq * 4);
                    if (I) { float sc = I[grow]; v.x *= sc; v.y *= sc; v.z *= sc; v.w *= sc; }
                }
                As[kq * 4 + 0][r] = v.x;
                As[kq * 4 + 1][r] = v.y;
                As[kq * 4 + 2][r] = v.z;
                As[kq * 4 + 3][r] = v.w;
            }
            // W tile: 32 k x 128 cols
#pragma unroll
            for (int i = 0; i < 4; i++) {
                int f = i * 256 + t;
                int kk = f >> 5;
                int cq = f & 31;
                *(float4*)&Bs[kk][cq * 4] =
                    *(const float4*)(W + (size_t)(k0 + kk) * 128 + cq * 4);
            }
            __syncthreads();
#pragma unroll
            for (int kk = 0; kk < 32; kk++) {
                float4 a = *(const float4*)&As[kk][trow * 4];
                // b pairs come straight out of LDS.128 as packed 64-bit
                ulonglong2 bq0 = *(const ulonglong2*)&Bs[kk][tcol * 8];
                ulonglong2 bq1 = *(const ulonglong2*)&Bs[kk][tcol * 8 + 4];
                unsigned long long bp[4] = {bq0.x, bq0.y, bq1.x, bq1.y};
                unsigned long long ap[4];
                ap[0] = dup_f32(a.x);
                ap[1] = dup_f32(a.y);
                ap[2] = dup_f32(a.z);
                ap[3] = dup_f32(a.w);
#pragma unroll
                for (int i = 0; i < 4; i++)
#pragma unroll
                    for (int j = 0; j < 4; j++) ffma2(acc[i][j], ap[i], bp[j]);
            }
        }
    }
    // epilogue: bias + relu + store
    int col = tcol * 8;
    float4 bA = *(const float4*)(bias + col);
    float4 bB = *(const float4*)(bias + col + 4);
    float bb[8] = {bA.x, bA.y, bA.z, bA.w, bB.x, bB.y, bB.z, bB.w};
#pragma unroll
    for (int i = 0; i < 4; i++) {
        int grow = row0 + trow * 4 + i;
        if (grow < M) {
            float o[8];
#pragma unroll
            for (int j = 0; j < 4; j++) {
                float lo, hi;
                unpack2(acc[i][j], lo, hi);
                o[2 * j] = fmaxf(lo + bb[2 * j], 0.f);
                o[2 * j + 1] = fmaxf(hi + bb[2 * j + 1], 0.f);
            }
            *(float4*)(C + (size_t)grow * 128 + col) = make_float4(o[0], o[1], o[2], o[3]);
            *(float4*)(C + (size_t)grow * 128 + col + 4) = make_float4(o[4], o[5], o[6], o[7]);
        }
    }
}

// ---------------- fused layer2 + classifier: out[i] = happ@Wsc + n1'@Wn1c + n2'@Wn2c + bc2 ----------------
__global__ __launch_bounds__(256) void final_kernel(float* __restrict__ out) {
    int gt = blockIdx.x * 256 + threadIdx.x;
    int i = gt >> 5;
    if (i >= NAPP) return;
    int lane = gt & 31;
    float4 h = ((const float4*)(g_happ + (size_t)i * D))[lane];
    float4 n1 = ((const float4*)(g_s1b + (size_t)i * D))[lane];
    float4 n2 = ((const float4*)(g_s2b + (size_t)i * D))[lane];
    float i1 = g_inv1[i], i2 = g_inv2[i];
    n1.x *= i1; n1.y *= i1; n1.z *= i1; n1.w *= i1;
    n2.x *= i2; n2.y *= i2; n2.z *= i2; n2.w *= i2;
    float hv[4] = {h.x, h.y, h.z, h.w};
    float n1v[4] = {n1.x, n1.y, n1.z, n1.w};
    float n2v[4] = {n2.x, n2.y, n2.z, n2.w};
    int k = lane * 4;
    float a0 = 0.f, a1 = 0.f;
#pragma unroll
    for (int c = 0; c < 4; c++) {
        a0 += hv[c] * g_Wsc[(k + c) * 2 + 0] + n1v[c] * g_Wn1c[(k + c) * 2 + 0] +
              n2v[c] * g_Wn2c[(k + c) * 2 + 0];
        a1 += hv[c] * g_Wsc[(k + c) * 2 + 1] + n1v[c] * g_Wn1c[(k + c) * 2 + 1] +
              n2v[c] * g_Wn2c[(k + c) * 2 + 1];
    }
#pragma unroll
    for (int off = 16; off; off >>= 1) {
        a0 += __shfl_down_sync(0xffffffffu, a0, off);
        a1 += __shfl_down_sync(0xffffffffu, a1, off);
    }
    if (lane == 0) {
        out[2 * i + 0] = a0 + g_bc2[0];
        out[2 * i + 1] = a1 + g_bc2[1];
    }
}

extern "C" void kernel_launch(void* const* d_in, const int* in_sizes, int n_in,
                              void* d_out, int out_size) {
    const float* x_app = (const float*)d_in[0];
    const float* x_attr = (const float*)d_in[1];
    const float* ew0 = (const float*)d_in[2];
    const float* ew1 = (const float*)d_in[3];
    const float* ew2 = (const float*)d_in[4];
    const float* Wself1 = (const float*)d_in[5];
    const float* Wneigh1 = (const float*)d_in[6];
    const float* b1 = (const float*)d_in[7];
    const float* Wself2 = (const float*)d_in[8];
    const float* Wneigh2 = (const float*)d_in[9];
    const float* b2 = (const float*)d_in[10];
    const float* Wc = (const float*)d_in[11];
    const float* bc = (const float*)d_in[12];
    const int* src0 = (const int*)d_in[13];
    const int* dst0 = (const int*)d_in[14];
    const int* src1 = (const int*)d_in[15];
    const int* dst1 = (const int*)d_in[16];
    const int* src2 = (const int*)d_in[17];
    const int* dst2 = (const int*)d_in[18];
    float* out = (float*)d_out;

    float *s0, *s1, *s2, *s1b, *s2b, *deg0, *deg1, *deg2;
    float *inv0, *inv1, *inv2, *hattr, *happ, *WappSelf, *bapp;
    cudaGetSymbolAddress((void**)&s0, g_s0);
    cudaGetSymbolAddress((void**)&s1, g_s1);
    cudaGetSymbolAddress((void**)&s2, g_s2);
    cudaGetSymbolAddress((void**)&s1b, g_s1b);
    cudaGetSymbolAddress((void**)&s2b, g_s2b);
    cudaGetSymbolAddress((void**)&deg0, g_deg0);
    cudaGetSymbolAddress((void**)&deg1, g_deg1);
    cudaGetSymbolAddress((void**)&deg2, g_deg2);
    cudaGetSymbolAddress((void**)&inv0, g_inv0);
    cudaGetSymbolAddress((void**)&inv1, g_inv1);
    cudaGetSymbolAddress((void**)&inv2, g_inv2);
    cudaGetSymbolAddress((void**)&hattr, g_hattr);
    cudaGetSymbolAddress((void**)&happ, g_happ);
    cudaGetSymbolAddress((void**)&WappSelf, g_WappSelf);
    cudaGetSymbolAddress((void**)&bapp, g_bapp);

    zero_kernel<<<2048, 256>>>();
    prep_kernel<<<1, 256>>>(Wself1, b1, Wself2, Wneigh2, b2, Wc, bc);

    const int SCATTER_BLOCKS = (NEDGE * 32) / 256;  // 62500
    // layer 1 aggregations
    scatter_kernel<<<SCATTER_BLOCKS, 256>>>(x_app, src0, dst0, ew0, s0, deg0);
    scatter_kernel<<<SCATTER_BLOCKS, 256>>>(x_attr, src1, dst1, ew1, s1, deg1);
    scatter_kernel<<<SCATTER_BLOCKS, 256>>>(x_app, src2, dst2, ew2, s2, deg2);
    invdeg_kernel<<<(NAPP + 255) / 256, 256>>>();

    // layer 1 dense (64-row tiles, FFMA2 inner loop)
    gemm_relu_kernel<<<(NATTR + 63) / 64, 256>>>(
        x_attr, nullptr, s0, inv0, nullptr, nullptr,
        Wself1, Wneigh1, nullptr, b1, hattr, NATTR, 2);
    gemm_relu_kernel<<<(NAPP + 63) / 64, 256>>>(
        x_app, nullptr, s1, inv1, s2, inv2,
        WappSelf, Wneigh1 + D * D, Wneigh1 + 2 * D * D, bapp, happ, NAPP, 3);

    // layer 2 aggregations (attr output of layer 2 is unused -> skipped)
    scatter_kernel<<<SCATTER_BLOCKS, 256>>>(hattr, src1, dst1, ew1, s1b, nullptr);
    scatter_kernel<<<SCATTER_BLOCKS, 256>>>(happ, src2, dst2, ew2, s2b, nullptr);

    // layer 2 + classifier fused (weights pre-folded through Wc)
    final_kernel<<<(NAPP * 32 + 255) / 256, 256>>>(out);
}

// round 14
// speedup vs baseline: 1.4446x; 1.1386x over previous
#include <cuda_runtime.h>
#include <cuda_bf16.h>
#include <cstddef>

#define NAPP 100000
#define NATTR 50000
#define NEDGE 500000
#define D 128

// ---------------- scratch (device globals; no allocation allowed) ----------------
__device__ __align__(256) float g_s0[NATTR * D];
__device__ __align__(256) float g_s1[NAPP * D];
__device__ __align__(256) float g_s2[NAPP * D];
__device__ __align__(256) float g_s1b[NAPP * D];
__device__ __align__(256) float g_s2b[NAPP * D];
__device__ __align__(256) float g_deg0[NATTR];
__device__ __align__(256) float g_deg1[NAPP];
__device__ __align__(256) float g_deg2[NAPP];
__device__ __align__(256) float g_inv0[NATTR];
__device__ __align__(256) float g_inv1[NAPP];
__device__ __align__(256) float g_inv2[NAPP];
__device__ __align__(256) float g_hattr[NATTR * D];
__device__ __align__(256) float g_happ[NAPP * D];
__device__ __align__(256) float g_WappSelf[D * D];
__device__ __align__(256) float g_bapp[D];
__device__ __align__(256) float g_Wsc[D * 2];
__device__ __align__(256) float g_Wn1c[D * 2];
__device__ __align__(256) float g_Wn2c[D * 2];
__device__ __align__(256) float g_bc2[2];

// ---------------- zero scratch accumulators ----------------
__global__ void zero_kernel() {
    size_t stride = (size_t)gridDim.x * blockDim.x;
    size_t gt = (size_t)blockIdx.x * blockDim.x + threadIdx.x;
    float4 z = make_float4(0.f, 0.f, 0.f, 0.f);
    for (size_t i = gt; i < (size_t)NATTR * D / 4; i += stride) ((float4*)g_s0)[i] = z;
    for (size_t i = gt; i < (size_t)NAPP * D / 4; i += stride) {
        ((float4*)g_s1)[i] = z;
        ((float4*)g_s2)[i] = z;
        ((float4*)g_s1b)[i] = z;
        ((float4*)g_s2b)[i] = z;
    }
    for (size_t i = gt; i < NAPP; i += stride) {
        g_deg1[i] = 0.f; g_deg2[i] = 0.f;
        if (i < NATTR) g_deg0[i] = 0.f;
    }
}

// ---------------- fold weights: Wself1[1]+Wself1[2], b1[1]+b1[2], and layer2@Wc ----------------
__global__ void prep_kernel(const float* __restrict__ Wself1, const float* __restrict__ b1,
                            const float* __restrict__ Wself2, const float* __restrict__ Wneigh2,
                            const float* __restrict__ b2, const float* __restrict__ Wc,
                            const float* __restrict__ bc) {
    int t = threadIdx.x;
    for (int idx = t; idx < D * D; idx += 256)
        g_WappSelf[idx] = Wself1[D * D + idx] + Wself1[2 * D * D + idx];
    if (t < D) g_bapp[t] = b1[D + t] + b1[2 * D + t];
    {
        int k = t >> 1, o = t & 1;
        float sWs = 0.f, sW1 = 0.f, sW2 = 0.f;
        for (int j = 0; j < D; j++) {
            float wc = Wc[j * 2 + o];
            sWs += (Wself2[D * D + k * D + j] + Wself2[2 * D * D + k * D + j]) * wc;
            sW1 += Wneigh2[D * D + k * D + j] * wc;
            sW2 += Wneigh2[2 * D * D + k * D + j] * wc;
        }
        g_Wsc[k * 2 + o] = sWs;
        g_Wn1c[k * 2 + o] = sW1;
        g_Wn2c[k * 2 + o] = sW2;
    }
    if (t < 2) {
        float s = bc[t];
        for (int j = 0; j < D; j++) s += (b2[D + j] + b2[2 * D + j]) * Wc[j * 2 + t];
        g_bc2[t] = s;
    }
}

// ---------------- edge scatter: s[dst] += ew * hsrc[src]; deg[dst] += 1 ----------------
__global__ __launch_bounds__(256) void scatter_kernel(
    const float* __restrict__ hsrc, const int* __restrict__ src,
    const int* __restrict__ dst, const float* __restrict__ ew,
    float* __restrict__ s, float* __restrict__ deg) {
    int gt = blockIdx.x * 256 + threadIdx.x;
    int e = gt >> 5;
    if (e >= NEDGE) return;
    int lane = gt & 31;
    int sR = __ldg(src + e);
    int dR = __ldg(dst + e);
    float w = __ldg(ew + e);
    float4 v = __ldg((const float4*)(hsrc + (size_t)sR * D) + lane);
    v.x *= w; v.y *= w; v.z *= w; v.w *= w;
    float* p = s + (size_t)dR * D + lane * 4;
    asm volatile("red.global.add.v4.f32 [%0], {%1,%2,%3,%4};"
                 :: "l"(p), "f"(v.x), "f"(v.y), "f"(v.z), "f"(v.w) : "memory");
    if (deg != nullptr && lane == 0) atomicAdd(deg + dR, 1.0f);
}

// ---------------- inv degree ----------------
__global__ void invdeg_kernel() {
    int i = blockIdx.x * 256 + threadIdx.x;
    if (i < NAPP) {
        g_inv1[i] = 1.0f / fmaxf(g_deg1[i], 1.0f);
        g_inv2[i] = 1.0f / fmaxf(g_deg2[i], 1.0f);
        if (i < NATTR) g_inv0[i] = 1.0f / fmaxf(g_deg0[i], 1.0f);
    }
}

// ---------------- bf16 split + mma helpers ----------------
__device__ __forceinline__ void split2(float x, float y, unsigned& hi, unsigned& lo) {
    __nv_bfloat16 hx = __float2bfloat16(x), hy = __float2bfloat16(y);
    float rx = x - __bfloat162float(hx), ry = y - __bfloat162float(hy);
    __nv_bfloat16 lx = __float2bfloat16(rx), ly = __float2bfloat16(ry);
    hi = ((unsigned)__bfloat16_as_ushort(hy) << 16) | (unsigned)__bfloat16_as_ushort(hx);
    lo = ((unsigned)__bfloat16_as_ushort(ly) << 16) | (unsigned)__bfloat16_as_ushort(lx);
}
__device__ __forceinline__ unsigned sptr(const void* p) {
    return (unsigned)__cvta_generic_to_shared(p);
}
#define LDSM4(R0, R1, R2, R3, ADDR)                                              \
    asm volatile("ldmatrix.sync.aligned.m8n8.x4.shared.b16 {%0,%1,%2,%3},[%4];"  \
                 : "=r"(R0), "=r"(R1), "=r"(R2), "=r"(R3) : "r"(ADDR))
__device__ __forceinline__ void mma16816(float* d, const unsigned* a, const unsigned* b) {
    asm volatile(
        "mma.sync.aligned.m16n8k16.row.col.f32.bf16.bf16.f32 "
        "{%0,%1,%2,%3}, {%4,%5,%6,%7}, {%8,%9}, {%0,%1,%2,%3};"
        : "+f"(d[0]), "+f"(d[1]), "+f"(d[2]), "+f"(d[3])
        : "r"(a[0]), "r"(a[1]), "r"(a[2]), "r"(a[3]), "r"(b[0]), "r"(b[1]));
}

// ---------------- tensor-core GEMM: C = relu( sum_j (A_j*scale_j) @ W_j + bias ) --------
// bf16 split precision: x = hi + lo; x@w = hi@wh + hi@wl + lo@wh (lo@wl dropped, ~2^-18).
// CTA: 128x128 tile, 256 threads = 8 warps in 4(m) x 2(n); warp tile 32x64.
// SK = 40 shorts = 80 bytes: row stride is 16B-aligned (ldmatrix requirement) and
// the 20-bank stride makes the 8-address ldmatrix phase conflict-free.
#define SK 40
__global__ __launch_bounds__(256) void gemm_mma_kernel(
    const float* __restrict__ A0, const float* __restrict__ I0,
    const float* __restrict__ A1, const float* __restrict__ I1,
    const float* __restrict__ A2, const float* __restrict__ I2,
    const float* __restrict__ W0, const float* __restrict__ W1, const float* __restrict__ W2,
    const float* __restrict__ bias, float* __restrict__ C, int M, int nin) {
    __shared__ __align__(16) unsigned short Ah[128 * SK];
    __shared__ __align__(16) unsigned short Al[128 * SK];
    __shared__ __align__(16) unsigned short Wh[128 * SK];
    __shared__ __align__(16) unsigned short Wl[128 * SK];
    const int t = threadIdx.x;
    const int lane = t & 31, wid = t >> 5;
    const int wm = wid & 3, wn = wid >> 2;
    const int row0 = blockIdx.x * 128;

    float d[2][8][4];
#pragma unroll
    for (int i = 0; i < 2; i++)
#pragma unroll
        for (int j = 0; j < 8; j++)
#pragma unroll
            for (int q = 0; q < 4; q++) d[i][j][q] = 0.f;

    // ldmatrix per-lane addressing (PTX m8n8.x4: lanes 0-7 -> matrix0 rows, 8-15 -> m1, ...)
    const int sel = lane >> 3, lr = lane & 7;
    const int a_row = (sel & 1) * 8 + lr;   // m0: rows 0-7 k0-7 | m1: rows 8-15 k0-7 | m2/m3: k8-15
    const int a_koff = (sel >> 1) * 8;
    const int b_col = (sel >> 1) * 8 + lr;  // m0: cols 0-7 k0-7 | m1: cols 0-7 k8-15 | m2/m3: cols 8-15
    const int b_koff = (sel & 1) * 8;

    const float* Aj[3] = {A0, A1, A2};
    const float* Ij[3] = {I0, I1, I2};
    const float* Wj[3] = {W0, W1, W2};

    for (int jj = 0; jj < nin; jj++) {
        const float* A = Aj[jj];
        const float* I = Ij[jj];
        const float* W = Wj[jj];
        for (int kc = 0; kc < 4; kc++) {
            const int k0 = kc * 32;
            __syncthreads();
            // ---- A chunk: 128 rows x 32 k fp32, coalesced, split to bf16 hi/lo ----
#pragma unroll
            for (int i = 0; i < 4; i++) {
                int f = i * 256 + t;
                int r = f >> 3;
                int kq = f & 7;
                int grow = row0 + r;
                float4 v = make_float4(0.f, 0.f, 0.f, 0.f);
                if (grow < M) {
                    v = *(const float4*)(A + (size_t)grow * 128 + k0 + kq * 4);
                    if (I) { float sc = I[grow]; v.x *= sc; v.y *= sc; v.z *= sc; v.w *= sc; }
                }
                unsigned h01, l01, h23, l23;
                split2(v.x, v.y, h01, l01);
                split2(v.z, v.w, h23, l23);
                *(uint2*)&Ah[r * SK + kq * 4] = make_uint2(h01, h23);
                *(uint2*)&Al[r * SK + kq * 4] = make_uint2(l01, l23);
            }
            // ---- W chunk: transpose to [n][k] col-major bf16 hi/lo (W stays L2-resident) ----
#pragma unroll
            for (int i = 0; i < 4; i++) {
                int f = i * 256 + t;
                int n = f & 127;
                int kq = f >> 7;  // 0..7
                int kb = k0 + kq * 4;
                float w0 = W[(size_t)(kb + 0) * 128 + n];
                float w1 = W[(size_t)(kb + 1) * 128 + n];
                float w2 = W[(size_t)(kb + 2) * 128 + n];
                float w3 = W[(size_t)(kb + 3) * 128 + n];
                unsigned h01, l01, h23, l23;
                split2(w0, w1, h01, l01);
                split2(w2, w3, h23, l23);
                *(uint2*)&Wh[n * SK + kq * 4] = make_uint2(h01, h23);
                *(uint2*)&Wl[n * SK + kq * 4] = make_uint2(l01, l23);
            }
            __syncthreads();
            // ---- split passes over this 32-k chunk ----
#pragma unroll
            for (int ks = 0; ks < 32; ks += 16) {
                unsigned ah[2][4], al[2][4], bh[8][2], bl[8][2];
#pragma unroll
                for (int mt = 0; mt < 2; mt++) {
                    unsigned addr = sptr(&Ah[(wm * 32 + mt * 16 + a_row) * SK + ks + a_koff]);
                    LDSM4(ah[mt][0], ah[mt][1], ah[mt][2], ah[mt][3], addr);
                    addr = sptr(&Al[(wm * 32 + mt * 16 + a_row) * SK + ks + a_koff]);
                    LDSM4(al[mt][0], al[mt][1], al[mt][2], al[mt][3], addr);
                }
#pragma unroll
                for (int bt = 0; bt < 4; bt++) {
                    unsigned addr = sptr(&Wh[(wn * 64 + bt * 16 + b_col) * SK + ks + b_koff]);
                    LDSM4(bh[2 * bt][0], bh[2 * bt][1], bh[2 * bt + 1][0], bh[2 * bt + 1][1], addr);
                    addr = sptr(&Wl[(wn * 64 + bt * 16 + b_col) * SK + ks + b_koff]);
                    LDSM4(bl[2 * bt][0], bl[2 * bt][1], bl[2 * bt + 1][0], bl[2 * bt + 1][1], addr);
                }
#pragma unroll
                for (int mt = 0; mt < 2; mt++)
#pragma unroll
                    for (int nt = 0; nt < 8; nt++) {
                        mma16816(d[mt][nt], ah[mt], bh[nt]);  // hi*hi
                        mma16816(d[mt][nt], ah[mt], bl[nt]);  // hi*lo
                        mma16816(d[mt][nt], al[mt], bh[nt]);  // lo*hi
                    }
            }
        }
    }
    // ---- epilogue: bias + relu + store (d0,d1 -> row g; d2,d3 -> row g+8) ----
    const int tig = lane & 3, grp = lane >> 2;
#pragma unroll
    for (int nt = 0; nt < 8; nt++) {
        int col = wn * 64 + nt * 8 + tig * 2;
        float b0 = bias[col], b1 = bias[col + 1];
#pragma unroll
        for (int mt = 0; mt < 2; mt++) {
            int r = row0 + wm * 32 + mt * 16 + grp;
            if (r < M)
                *(float2*)(C + (size_t)r * 128 + col) =
                    make_float2(fmaxf(d[mt][nt][0] + b0, 0.f), fmaxf(d[mt][nt][1] + b1, 0.f));
            if (r + 8 < M)
                *(float2*)(C + (size_t)(r + 8) * 128 + col) =
                    make_float2(fmaxf(d[mt][nt][2] + b0, 0.f), fmaxf(d[mt][nt][3] + b1, 0.f));
        }
    }
}

// ---------------- fused layer2 + classifier: out[i] = happ@Wsc + n1'@Wn1c + n2'@Wn2c + bc2 ----------------
__global__ __launch_bounds__(256) void final_kernel(float* __restrict__ out) {
    int gt = blockIdx.x * 256 + threadIdx.x;
    int i = gt >> 5;
    if (i >= NAPP) return;
    int lane = gt & 31;
    float4 h = ((const float4*)(g_happ + (size_t)i * D))[lane];
    float4 n1 = ((const float4*)(g_s1b + (size_t)i * D))[lane];
    float4 n2 = ((const float4*)(g_s2b + (size_t)i * D))[lane];
    float i1 = g_inv1[i], i2 = g_inv2[i];
    n1.x *= i1; n1.y *= i1; n1.z *= i1; n1.w *= i1;
    n2.x *= i2; n2.y *= i2; n2.z *= i2; n2.w *= i2;
    float hv[4] = {h.x, h.y, h.z, h.w};
    float n1v[4] = {n1.x, n1.y, n1.z, n1.w};
    float n2v[4] = {n2.x, n2.y, n2.z, n2.w};
    int k = lane * 4;
    float a0 = 0.f, a1 = 0.f;
#pragma unroll
    for (int c = 0; c < 4; c++) {
        a0 += hv[c] * g_Wsc[(k + c) * 2 + 0] + n1v[c] * g_Wn1c[(k + c) * 2 + 0] +
              n2v[c] * g_Wn2c[(k + c) * 2 + 0];
        a1 += hv[c] * g_Wsc[(k + c) * 2 + 1] + n1v[c] * g_Wn1c[(k + c) * 2 + 1] +
              n2v[c] * g_Wn2c[(k + c) * 2 + 1];
    }
#pragma unroll
    for (int off = 16; off; off >>= 1) {
        a0 += __shfl_down_sync(0xffffffffu, a0, off);
        a1 += __shfl_down_sync(0xffffffffu, a1, off);
    }
    if (lane == 0) {
        out[2 * i + 0] = a0 + g_bc2[0];
        out[2 * i + 1] = a1 + g_bc2[1];
    }
}

extern "C" void kernel_launch(void* const* d_in, const int* in_sizes, int n_in,
                              void* d_out, int out_size) {
    const float* x_app = (const float*)d_in[0];
    const float* x_attr = (const float*)d_in[1];
    const float* ew0 = (const float*)d_in[2];
    const float* ew1 = (const float*)d_in[3];
    const float* ew2 = (const float*)d_in[4];
    const float* Wself1 = (const float*)d_in[5];
    const float* Wneigh1 = (const float*)d_in[6];
    const float* b1 = (const float*)d_in[7];
    const float* Wself2 = (const float*)d_in[8];
    const float* Wneigh2 = (const float*)d_in[9];
    const float* b2 = (const float*)d_in[10];
    const float* Wc = (const float*)d_in[11];
    const float* bc = (const float*)d_in[12];
    const int* src0 = (const int*)d_in[13];
    const int* dst0 = (const int*)d_in[14];
    const int* src1 = (const int*)d_in[15];
    const int* dst1 = (const int*)d_in[16];
    const int* src2 = (const int*)d_in[17];
    const int* dst2 = (const int*)d_in[18];
    float* out = (float*)d_out;

    float *s0, *s1, *s2, *s1b, *s2b, *deg0, *deg1, *deg2;
    float *inv0, *inv1, *inv2, *hattr, *happ, *WappSelf, *bapp;
    cudaGetSymbolAddress((void**)&s0, g_s0);
    cudaGetSymbolAddress((void**)&s1, g_s1);
    cudaGetSymbolAddress((void**)&s2, g_s2);
    cudaGetSymbolAddress((void**)&s1b, g_s1b);
    cudaGetSymbolAddress((void**)&s2b, g_s2b);
    cudaGetSymbolAddress((void**)&deg0, g_deg0);
    cudaGetSymbolAddress((void**)&deg1, g_deg1);
    cudaGetSymbolAddress((void**)&deg2, g_deg2);
    cudaGetSymbolAddress((void**)&inv0, g_inv0);
    cudaGetSymbolAddress((void**)&inv1, g_inv1);
    cudaGetSymbolAddress((void**)&inv2, g_inv2);
    cudaGetSymbolAddress((void**)&hattr, g_hattr);
    cudaGetSymbolAddress((void**)&happ, g_happ);
    cudaGetSymbolAddress((void**)&WappSelf, g_WappSelf);
    cudaGetSymbolAddress((void**)&bapp, g_bapp);

    zero_kernel<<<2048, 256>>>();
    prep_kernel<<<1, 256>>>(Wself1, b1, Wself2, Wneigh2, b2, Wc, bc);

    const int SCATTER_BLOCKS = (NEDGE * 32) / 256;  // 62500
    // layer 1 aggregations
    scatter_kernel<<<SCATTER_BLOCKS, 256>>>(x_app, src0, dst0, ew0, s0, deg0);
    scatter_kernel<<<SCATTER_BLOCKS, 256>>>(x_attr, src1, dst1, ew1, s1, deg1);
    scatter_kernel<<<SCATTER_BLOCKS, 256>>>(x_app, src2, dst2, ew2, s2, deg2);
    invdeg_kernel<<<(NAPP + 255) / 256, 256>>>();

    // layer 1 dense — bf16-split tensor-core GEMMs (128-row tiles)
    gemm_mma_kernel<<<(NATTR + 127) / 128, 256>>>(
        x_attr, nullptr, s0, inv0, nullptr, nullptr,
        Wself1, Wneigh1, nullptr, b1, hattr, NATTR, 2);
    gemm_mma_kernel<<<(NAPP + 127) / 128, 256>>>(
        x_app, nullptr, s1, inv1, s2, inv2,
        WappSelf, Wneigh1 + D * D, Wneigh1 + 2 * D * D, bapp, happ, NAPP, 3);

    // layer 2 aggregations (attr output of layer 2 is unused -> skipped)
    scatter_kernel<<<SCATTER_BLOCKS, 256>>>(hattr, src1, dst1, ew1, s1b, nullptr);
    scatter_kernel<<<SCATTER_BLOCKS, 256>>>(happ, src2, dst2, ew2, s2b, nullptr);

    // layer 2 + classifier fused (weights pre-folded through Wc)
    final_kernel<<<(NAPP * 32 + 255) / 256, 256>>>(out);
}

// round 15
// speedup vs baseline: 1.5955x; 1.1045x over previous
#include <cuda_runtime.h>
#include <cuda_bf16.h>
#include <cstddef>

#define NAPP 100000
#define NATTR 50000
#define NEDGE 500000
#define D 128

// ---------------- scratch (device globals; no allocation allowed) ----------------
__device__ __align__(256) float g_s0[NATTR * D];
__device__ __align__(256) float g_s1[NAPP * D];
__device__ __align__(256) float g_s2[NAPP * D];
__device__ __align__(256) float g_s1b[NAPP * D];
__device__ __align__(256) float g_s2b[NAPP * D];
__device__ __align__(256) float g_deg0[NATTR];
__device__ __align__(256) float g_deg1[NAPP];
__device__ __align__(256) float g_deg2[NAPP];
__device__ __align__(256) float g_inv0[NATTR];
__device__ __align__(256) float g_inv1[NAPP];
__device__ __align__(256) float g_inv2[NAPP];
__device__ __align__(256) float g_hattr[NATTR * D];
__device__ __align__(256) float g_happ[NAPP * D];
__device__ __align__(256) float g_bapp[D];
__device__ __align__(256) float g_Wsc[D * 2];
__device__ __align__(256) float g_Wn1c[D * 2];
__device__ __align__(256) float g_Wn2c[D * 2];
__device__ __align__(256) float g_bc2[2];
// pre-split weights, [mat][n=128][k=128] bf16 hi/lo. mats:
// 0: Wself1[0]  1: Wneigh1[0]  2: Wself1[1]+Wself1[2]  3: Wneigh1[1]  4: Wneigh1[2]
__device__ __align__(256) unsigned short g_Whi[5 * 128 * 128];
__device__ __align__(256) unsigned short g_Wlo[5 * 128 * 128];

// ---------------- zero scratch accumulators ----------------
__global__ void zero_kernel() {
    size_t stride = (size_t)gridDim.x * blockDim.x;
    size_t gt = (size_t)blockIdx.x * blockDim.x + threadIdx.x;
    float4 z = make_float4(0.f, 0.f, 0.f, 0.f);
    for (size_t i = gt; i < (size_t)NATTR * D / 4; i += stride) ((float4*)g_s0)[i] = z;
    for (size_t i = gt; i < (size_t)NAPP * D / 4; i += stride) {
        ((float4*)g_s1)[i] = z;
        ((float4*)g_s2)[i] = z;
        ((float4*)g_s1b)[i] = z;
        ((float4*)g_s2b)[i] = z;
    }
    for (size_t i = gt; i < NAPP; i += stride) {
        g_deg1[i] = 0.f; g_deg2[i] = 0.f;
        if (i < NATTR) g_deg0[i] = 0.f;
    }
}

// ---------------- bf16 split helper ----------------
__device__ __forceinline__ void split2(float x, float y, unsigned& hi, unsigned& lo) {
    __nv_bfloat16 hx = __float2bfloat16(x), hy = __float2bfloat16(y);
    float rx = x - __bfloat162float(hx), ry = y - __bfloat162float(hy);
    __nv_bfloat16 lx = __float2bfloat16(rx), ly = __float2bfloat16(ry);
    hi = ((unsigned)__bfloat16_as_ushort(hy) << 16) | (unsigned)__bfloat16_as_ushort(hx);
    lo = ((unsigned)__bfloat16_as_ushort(ly) << 16) | (unsigned)__bfloat16_as_ushort(lx);
}

// ---------------- fold biases + classifier weights ----------------
__global__ void prep_kernel(const float* __restrict__ b1,
                            const float* __restrict__ Wself2, const float* __restrict__ Wneigh2,
                            const float* __restrict__ b2, const float* __restrict__ Wc,
                            const float* __restrict__ bc) {
    int t = threadIdx.x;
    if (t < D) g_bapp[t] = b1[D + t] + b1[2 * D + t];
    {
        int k = t >> 1, o = t & 1;
        float sWs = 0.f, sW1 = 0.f, sW2 = 0.f;
        for (int j = 0; j < D; j++) {
            float wc = Wc[j * 2 + o];
            sWs += (Wself2[D * D + k * D + j] + Wself2[2 * D * D + k * D + j]) * wc;
            sW1 += Wneigh2[D * D + k * D + j] * wc;
            sW2 += Wneigh2[2 * D * D + k * D + j] * wc;
        }
        g_Wsc[k * 2 + o] = sWs;
        g_Wn1c[k * 2 + o] = sW1;
        g_Wn2c[k * 2 + o] = sW2;
    }
    if (t < 2) {
        float s = bc[t];
        for (int j = 0; j < D; j++) s += (b2[D + j] + b2[2 * D + j]) * Wc[j * 2 + t];
        g_bc2[t] = s;
    }
}

// ---------------- transpose + bf16-split layer-1 weights (once) ----------------
__global__ void wsplit_kernel(const float* __restrict__ Wself1,
                              const float* __restrict__ Wneigh1) {
    int m = blockIdx.x >> 5;    // 0..4
    int part = blockIdx.x & 31;
    int f = part * 512 + threadIdx.x * 2;
    int n = f >> 7, k = f & 127;  // k even
    float w0, w1;
    if (m == 2) {
        w0 = Wself1[D * D + k * D + n] + Wself1[2 * D * D + k * D + n];
        w1 = Wself1[D * D + (k + 1) * D + n] + Wself1[2 * D * D + (k + 1) * D + n];
    } else {
        const float* src = (m == 0) ? Wself1
                         : (m == 1) ? Wneigh1
                         : (m == 3) ? (Wneigh1 + D * D) : (Wneigh1 + 2 * D * D);
        w0 = src[k * D + n];
        w1 = src[(k + 1) * D + n];
    }
    unsigned hi, lo;
    split2(w0, w1, hi, lo);
    *(unsigned*)&g_Whi[m * 16384 + n * 128 + k] = hi;
    *(unsigned*)&g_Wlo[m * 16384 + n * 128 + k] = lo;
}

// ---------------- edge scatter: s[dst] += ew * hsrc[src]; deg[dst] += 1 ----------------
__global__ __launch_bounds__(256) void scatter_kernel(
    const float* __restrict__ hsrc, const int* __restrict__ src,
    const int* __restrict__ dst, const float* __restrict__ ew,
    float* __restrict__ s, float* __restrict__ deg) {
    int gt = blockIdx.x * 256 + threadIdx.x;
    int e = gt >> 5;
    if (e >= NEDGE) return;
    int lane = gt & 31;
    int sR = __ldg(src + e);
    int dR = __ldg(dst + e);
    float w = __ldg(ew + e);
    float4 v = __ldg((const float4*)(hsrc + (size_t)sR * D) + lane);
    v.x *= w; v.y *= w; v.z *= w; v.w *= w;
    float* p = s + (size_t)dR * D + lane * 4;
    asm volatile("red.global.add.v4.f32 [%0], {%1,%2,%3,%4};"
                 :: "l"(p), "f"(v.x), "f"(v.y), "f"(v.z), "f"(v.w) : "memory");
    if (deg != nullptr && lane == 0) atomicAdd(deg + dR, 1.0f);
}

// ---------------- inv degree ----------------
__global__ void invdeg_kernel() {
    int i = blockIdx.x * 256 + threadIdx.x;
    if (i < NAPP) {
        g_inv1[i] = 1.0f / fmaxf(g_deg1[i], 1.0f);
        g_inv2[i] = 1.0f / fmaxf(g_deg2[i], 1.0f);
        if (i < NATTR) g_inv0[i] = 1.0f / fmaxf(g_deg0[i], 1.0f);
    }
}

// ---------------- mma helpers ----------------
__device__ __forceinline__ unsigned sptr(const void* p) {
    return (unsigned)__cvta_generic_to_shared(p);
}
__device__ __forceinline__ void cp16(void* dst, const void* src) {
    asm volatile("cp.async.ca.shared.global [%0], [%1], 16;"
                 :: "r"(sptr(dst)), "l"(src) : "memory");
}
#define CP_COMMIT() asm volatile("cp.async.commit_group;" ::: "memory")
#define CP_WAIT0() asm volatile("cp.async.wait_group 0;" ::: "memory")
#define LDSM4(R0, R1, R2, R3, ADDR)                                              \
    asm volatile("ldmatrix.sync.aligned.m8n8.x4.shared.b16 {%0,%1,%2,%3},[%4];"  \
                 : "=r"(R0), "=r"(R1), "=r"(R2), "=r"(R3) : "r"(ADDR))
__device__ __forceinline__ void mma16816(float* d, const unsigned* a, const unsigned* b) {
    asm volatile(
        "mma.sync.aligned.m16n8k16.row.col.f32.bf16.bf16.f32 "
        "{%0,%1,%2,%3}, {%4,%5,%6,%7}, {%8,%9}, {%0,%1,%2,%3};"
        : "+f"(d[0]), "+f"(d[1]), "+f"(d[2]), "+f"(d[3])
        : "r"(a[0]), "r"(a[1]), "r"(a[2]), "r"(a[3]), "r"(b[0]), "r"(b[1]));
}

// ---------------- tensor-core GEMM: C = relu( sum_j (A_j*scale_j) @ Wj + bias ) --------
// bf16 split: x@w = hi@wh + hi@wl + lo@wh (lo@wl dropped, ~2^-18).
// Weights pre-split/pre-transposed in global bf16 -> cp.async straight to smem.
// A chunk prefetched into registers, overlapping the previous chunk's MMA.
#define SK 40  // 80B row stride: 16B-aligned, conflict-free ldmatrix phases
__global__ __launch_bounds__(256) void gemm_mma_kernel(
    const float* __restrict__ A0, const float* __restrict__ I0,
    const float* __restrict__ A1, const float* __restrict__ I1,
    const float* __restrict__ A2, const float* __restrict__ I2,
    const unsigned short* __restrict__ Wh0, const unsigned short* __restrict__ Wh1,
    const unsigned short* __restrict__ Wh2,
    const unsigned short* __restrict__ Wl0, const unsigned short* __restrict__ Wl1,
    const unsigned short* __restrict__ Wl2,
    const float* __restrict__ bias, float* __restrict__ C, int M, int nin) {
    __shared__ __align__(16) unsigned short Ah[128 * SK];
    __shared__ __align__(16) unsigned short Al[128 * SK];
    __shared__ __align__(16) unsigned short Wh[128 * SK];
    __shared__ __align__(16) unsigned short Wl[128 * SK];
    const int t = threadIdx.x;
    const int lane = t & 31, wid = t >> 5;
    const int wm = wid & 3, wn = wid >> 2;
    const int row0 = blockIdx.x * 128;

    float d[2][8][4];
#pragma unroll
    for (int i = 0; i < 2; i++)
#pragma unroll
        for (int j = 0; j < 8; j++)
#pragma unroll
            for (int q = 0; q < 4; q++) d[i][j][q] = 0.f;

    const int sel = lane >> 3, lr = lane & 7;
    const int a_row = (sel & 1) * 8 + lr;
    const int a_koff = (sel >> 1) * 8;
    const int b_col = (sel >> 1) * 8 + lr;
    const int b_koff = (sel & 1) * 8;

    const float* Aj[3] = {A0, A1, A2};
    const float* Ij[3] = {I0, I1, I2};
    const unsigned short* Whj[3] = {Wh0, Wh1, Wh2};
    const unsigned short* Wlj[3] = {Wl0, Wl1, Wl2};

    float4 va[4];
    auto loadA = [&](int it) {
        int jj = it >> 2, kc = it & 3, k0 = kc * 32;
        const float* A = Aj[jj];
        const float* I = Ij[jj];
#pragma unroll
        for (int i = 0; i < 4; i++) {
            int f = i * 256 + t;
            int r = f >> 3;
            int kq = f & 7;
            int grow = row0 + r;
            float4 v = make_float4(0.f, 0.f, 0.f, 0.f);
            if (grow < M) {
                v = *(const float4*)(A + (size_t)grow * 128 + k0 + kq * 4);
                if (I) { float sc = I[grow]; v.x *= sc; v.y *= sc; v.z *= sc; v.w *= sc; }
            }
            va[i] = v;
        }
    };

    const int total = nin * 4;
    loadA(0);
    for (int it = 0; it < total; it++) {
        int jj = it >> 2, kc = it & 3, k0 = kc * 32;
        __syncthreads();  // previous MMA done reading smem
        // ---- A: split prefetched regs into smem ----
#pragma unroll
        for (int i = 0; i < 4; i++) {
            int f = i * 256 + t;
            int r = f >> 3;
            int kq = f & 7;
            unsigned h01, l01, h23, l23;
            split2(va[i].x, va[i].y, h01, l01);
            split2(va[i].z, va[i].w, h23, l23);
            *(uint2*)&Ah[r * SK + kq * 4] = make_uint2(h01, h23);
            *(uint2*)&Al[r * SK + kq * 4] = make_uint2(l01, l23);
        }
        // ---- W: cp.async 16B chunks from pre-split bf16 ----
        const unsigned short* WhG = Whj[jj];
        const unsigned short* WlG = Wlj[jj];
#pragma unroll
        for (int i = 0; i < 2; i++) {
            int f = i * 256 + t;
            int n = f >> 2;
            int q = f & 3;
            cp16(&Wh[n * SK + q * 8], WhG + n * 128 + k0 + q * 8);
            cp16(&Wl[n * SK + q * 8], WlG + n * 128 + k0 + q * 8);
        }
        CP_COMMIT();
        if (it + 1 < total) loadA(it + 1);  // prefetch next A chunk
        CP_WAIT0();
        __syncthreads();
        // ---- MMA over this 32-k chunk (3 split passes) ----
#pragma unroll
        for (int ks = 0; ks < 32; ks += 16) {
            unsigned ah[2][4], al[2][4], bh[8][2], bl[8][2];
#pragma unroll
            for (int mt = 0; mt < 2; mt++) {
                unsigned addr = sptr(&Ah[(wm * 32 + mt * 16 + a_row) * SK + ks + a_koff]);
                LDSM4(ah[mt][0], ah[mt][1], ah[mt][2], ah[mt][3], addr);
                addr = sptr(&Al[(wm * 32 + mt * 16 + a_row) * SK + ks + a_koff]);
                LDSM4(al[mt][0], al[mt][1], al[mt][2], al[mt][3], addr);
            }
#pragma unroll
            for (int bt = 0; bt < 4; bt++) {
                unsigned addr = sptr(&Wh[(wn * 64 + bt * 16 + b_col) * SK + ks + b_koff]);
                LDSM4(bh[2 * bt][0], bh[2 * bt][1], bh[2 * bt + 1][0], bh[2 * bt + 1][1], addr);
                addr = sptr(&Wl[(wn * 64 + bt * 16 + b_col) * SK + ks + b_koff]);
                LDSM4(bl[2 * bt][0], bl[2 * bt][1], bl[2 * bt + 1][0], bl[2 * bt + 1][1], addr);
            }
#pragma unroll
            for (int mt = 0; mt < 2; mt++)
#pragma unroll
                for (int nt = 0; nt < 8; nt++) {
                    mma16816(d[mt][nt], ah[mt], bh[nt]);  // hi*hi
                    mma16816(d[mt][nt], ah[mt], bl[nt]);  // hi*lo
                    mma16816(d[mt][nt], al[mt], bh[nt]);  // lo*hi
                }
        }
    }
    // ---- epilogue: bias + relu + store ----
    const int tig = lane & 3, grp = lane >> 2;
#pragma unroll
    for (int nt = 0; nt < 8; nt++) {
        int col = wn * 64 + nt * 8 + tig * 2;
        float b0 = bias[col], b1 = bias[col + 1];
#pragma unroll
        for (int mt = 0; mt < 2; mt++) {
            int r = row0 + wm * 32 + mt * 16 + grp;
            if (r < M)
                *(float2*)(C + (size_t)r * 128 + col) =
                    make_float2(fmaxf(d[mt][nt][0] + b0, 0.f), fmaxf(d[mt][nt][1] + b1, 0.f));
            if (r + 8 < M)
                *(float2*)(C + (size_t)(r + 8) * 128 + col) =
                    make_float2(fmaxf(d[mt][nt][2] + b0, 0.f), fmaxf(d[mt][nt][3] + b1, 0.f));
        }
    }
}

// ---------------- fused layer2 + classifier: out[i] = happ@Wsc + n1'@Wn1c + n2'@Wn2c + bc2 ----------------
__global__ __launch_bounds__(256) void final_kernel(float* __restrict__ out) {
    int gt = blockIdx.x * 256 + threadIdx.x;
    int i = gt >> 5;
    if (i >= NAPP) return;
    int lane = gt & 31;
    float4 h = ((const float4*)(g_happ + (size_t)i * D))[lane];
    float4 n1 = ((const float4*)(g_s1b + (size_t)i * D))[lane];
    float4 n2 = ((const float4*)(g_s2b + (size_t)i * D))[lane];
    float i1 = g_inv1[i], i2 = g_inv2[i];
    n1.x *= i1; n1.y *= i1; n1.z *= i1; n1.w *= i1;
    n2.x *= i2; n2.y *= i2; n2.z *= i2; n2.w *= i2;
    float hv[4] = {h.x, h.y, h.z, h.w};
    float n1v[4] = {n1.x, n1.y, n1.z, n1.w};
    float n2v[4] = {n2.x, n2.y, n2.z, n2.w};
    int k = lane * 4;
    float a0 = 0.f, a1 = 0.f;
#pragma unroll
    for (int c = 0; c < 4; c++) {
        a0 += hv[c] * g_Wsc[(k + c) * 2 + 0] + n1v[c] * g_Wn1c[(k + c) * 2 + 0] +
              n2v[c] * g_Wn2c[(k + c) * 2 + 0];
        a1 += hv[c] * g_Wsc[(k + c) * 2 + 1] + n1v[c] * g_Wn1c[(k + c) * 2 + 1] +
              n2v[c] * g_Wn2c[(k + c) * 2 + 1];
    }
#pragma unroll
    for (int off = 16; off; off >>= 1) {
        a0 += __shfl_down_sync(0xffffffffu, a0, off);
        a1 += __shfl_down_sync(0xffffffffu, a1, off);
    }
    if (lane == 0) {
        out[2 * i + 0] = a0 + g_bc2[0];
        out[2 * i + 1] = a1 + g_bc2[1];
    }
}

extern "C" void kernel_launch(void* const* d_in, const int* in_sizes, int n_in,
                              void* d_out, int out_size) {
    const float* x_app = (const float*)d_in[0];
    const float* x_attr = (const float*)d_in[1];
    const float* ew0 = (const float*)d_in[2];
    const float* ew1 = (const float*)d_in[3];
    const float* ew2 = (const float*)d_in[4];
    const float* Wself1 = (const float*)d_in[5];
    const float* Wneigh1 = (const float*)d_in[6];
    const float* b1 = (const float*)d_in[7];
    const float* Wself2 = (const float*)d_in[8];
    const float* Wneigh2 = (const float*)d_in[9];
    const float* b2 = (const float*)d_in[10];
    const float* Wc = (const float*)d_in[11];
    const float* bc = (const float*)d_in[12];
    const int* src0 = (const int*)d_in[13];
    const int* dst0 = (const int*)d_in[14];
    const int* src1 = (const int*)d_in[15];
    const int* dst1 = (const int*)d_in[16];
    const int* src2 = (const int*)d_in[17];
    const int* dst2 = (const int*)d_in[18];
    float* out = (float*)d_out;

    float *s0, *s1, *s2, *s1b, *s2b;
    float *inv0, *inv1, *inv2, *hattr, *happ, *deg0, *deg1, *deg2;
    unsigned short *whi, *wlo;
    cudaGetSymbolAddress((void**)&s0, g_s0);
    cudaGetSymbolAddress((void**)&s1, g_s1);
    cudaGetSymbolAddress((void**)&s2, g_s2);
    cudaGetSymbolAddress((void**)&s1b, g_s1b);
    cudaGetSymbolAddress((void**)&s2b, g_s2b);
    cudaGetSymbolAddress((void**)&deg0, g_deg0);
    cudaGetSymbolAddress((void**)&deg1, g_deg1);
    cudaGetSymbolAddress((void**)&deg2, g_deg2);
    cudaGetSymbolAddress((void**)&inv0, g_inv0);
    cudaGetSymbolAddress((void**)&inv1, g_inv1);
    cudaGetSymbolAddress((void**)&inv2, g_inv2);
    cudaGetSymbolAddress((void**)&hattr, g_hattr);
    cudaGetSymbolAddress((void**)&happ, g_happ);
    cudaGetSymbolAddress((void**)&whi, g_Whi);
    cudaGetSymbolAddress((void**)&wlo, g_Wlo);
    float* bapp;
    cudaGetSymbolAddress((void**)&bapp, g_bapp);

    zero_kernel<<<2048, 256>>>();
    prep_kernel<<<1, 256>>>(b1, Wself2, Wneigh2, b2, Wc, bc);
    wsplit_kernel<<<160, 256>>>(Wself1, Wneigh1);

    const int SCATTER_BLOCKS = (NEDGE * 32) / 256;  // 62500
    // layer 1 aggregations
    scatter_kernel<<<SCATTER_BLOCKS, 256>>>(x_app, src0, dst0, ew0, s0, deg0);
    scatter_kernel<<<SCATTER_BLOCKS, 256>>>(x_attr, src1, dst1, ew1, s1, deg1);
    scatter_kernel<<<SCATTER_BLOCKS, 256>>>(x_app, src2, dst2, ew2, s2, deg2);
    invdeg_kernel<<<(NAPP + 255) / 256, 256>>>();

    const int MATSZ = 128 * 128;
    // layer 1 dense — pipelined bf16-split tensor-core GEMMs
    gemm_mma_kernel<<<(NATTR + 127) / 128, 256>>>(
        x_attr, nullptr, s0, inv0, nullptr, nullptr,
        whi + 0 * MATSZ, whi + 1 * MATSZ, nullptr,
        wlo + 0 * MATSZ, wlo + 1 * MATSZ, nullptr,
        b1, hattr, NATTR, 2);
    gemm_mma_kernel<<<(NAPP + 127) / 128, 256>>>(
        x_app, nullptr, s1, inv1, s2, inv2,
        whi + 2 * MATSZ, whi + 3 * MATSZ, whi + 4 * MATSZ,
        wlo + 2 * MATSZ, wlo + 3 * MATSZ, wlo + 4 * MATSZ,
        bapp, happ, NAPP, 3);

    // layer 2 aggregations (attr output of layer 2 is unused -> skipped)
    scatter_kernel<<<SCATTER_BLOCKS, 256>>>(hattr, src1, dst1, ew1, s1b, nullptr);
    scatter_kernel<<<SCATTER_BLOCKS, 256>>>(happ, src2, dst2, ew2, s2b, nullptr);

    // layer 2 + classifier fused (weights pre-folded through Wc)
    final_kernel<<<(NAPP * 32 + 255) / 256, 256>>>(out);
}

// round 16
// speedup vs baseline: 2.0010x; 1.2541x over previous
#include <cuda_runtime.h>
#include <cuda_bf16.h>
#include <cstddef>

#define NAPP 100000
#define NATTR 50000
#define NEDGE 500000
#define D 128

// ---------------- scratch (device globals; no allocation allowed) ----------------
__device__ __align__(256) float g_s0[NATTR * D];
__device__ __align__(256) float g_s1[NAPP * D];
__device__ __align__(256) float g_s2[NAPP * D];
__device__ __align__(256) float g_deg0[NATTR];
__device__ __align__(256) float g_deg1[NAPP];
__device__ __align__(256) float g_deg2[NAPP];
__device__ __align__(256) float g_inv0[NATTR];
__device__ __align__(256) float g_inv1[NAPP];
__device__ __align__(256) float g_inv2[NAPP];
// projected hidden states: [row][4] fp32.
// hattrP: cols 0-1 = hattr @ Wn1c (scattered over rel1)
// happP : cols 0-1 = happ @ Wsc (self term), cols 2-3 = happ @ Wn2c (scattered over rel2)
__device__ __align__(256) float g_hattrP[NATTR * 4];
__device__ __align__(256) float g_happP[NAPP * 4];
__device__ __align__(256) float g_acc1[NAPP * 2];
__device__ __align__(256) float g_acc2[NAPP * 2];
__device__ __align__(256) float g_bapp[D];
__device__ __align__(256) float g_Wsc[D * 2];
__device__ __align__(256) float g_Wn1c[D * 2];
__device__ __align__(256) float g_Wn2c[D * 2];
__device__ __align__(256) float g_bc2[2];
// pre-split weights, [mat][n=128][k=128] bf16 hi/lo. mats:
// 0: Wself1[0]  1: Wneigh1[0]  2: Wself1[1]+Wself1[2]  3: Wneigh1[1]  4: Wneigh1[2]
__device__ __align__(256) unsigned short g_Whi[5 * 128 * 128];
__device__ __align__(256) unsigned short g_Wlo[5 * 128 * 128];

// ---------------- zero scratch accumulators ----------------
__global__ void zero_kernel() {
    size_t stride = (size_t)gridDim.x * blockDim.x;
    size_t gt = (size_t)blockIdx.x * blockDim.x + threadIdx.x;
    float4 z = make_float4(0.f, 0.f, 0.f, 0.f);
    for (size_t i = gt; i < (size_t)NATTR * D / 4; i += stride) ((float4*)g_s0)[i] = z;
    for (size_t i = gt; i < (size_t)NAPP * D / 4; i += stride) {
        ((float4*)g_s1)[i] = z;
        ((float4*)g_s2)[i] = z;
    }
    for (size_t i = gt; i < NAPP; i += stride) {
        ((float4*)g_happP)[i] = z;
        if (i < NATTR) ((float4*)g_hattrP)[i] = z;
        if (i < NAPP / 2) { ((float4*)g_acc1)[i] = z; ((float4*)g_acc2)[i] = z; }
        g_deg1[i] = 0.f; g_deg2[i] = 0.f;
        if (i < NATTR) g_deg0[i] = 0.f;
    }
}

// ---------------- bf16 split helper ----------------
__device__ __forceinline__ void split2(float x, float y, unsigned& hi, unsigned& lo) {
    __nv_bfloat16 hx = __float2bfloat16(x), hy = __float2bfloat16(y);
    float rx = x - __bfloat162float(hx), ry = y - __bfloat162float(hy);
    __nv_bfloat16 lx = __float2bfloat16(rx), ly = __float2bfloat16(ry);
    hi = ((unsigned)__bfloat16_as_ushort(hy) << 16) | (unsigned)__bfloat16_as_ushort(hx);
    lo = ((unsigned)__bfloat16_as_ushort(ly) << 16) | (unsigned)__bfloat16_as_ushort(lx);
}

// ---------------- fold biases + classifier weights ----------------
__global__ void prep_kernel(const float* __restrict__ b1,
                            const float* __restrict__ Wself2, const float* __restrict__ Wneigh2,
                            const float* __restrict__ b2, const float* __restrict__ Wc,
                            const float* __restrict__ bc) {
    int t = threadIdx.x;
    if (t < D) g_bapp[t] = b1[D + t] + b1[2 * D + t];
    {
        int k = t >> 1, o = t & 1;
        float sWs = 0.f, sW1 = 0.f, sW2 = 0.f;
        for (int j = 0; j < D; j++) {
            float wc = Wc[j * 2 + o];
            sWs += (Wself2[D * D + k * D + j] + Wself2[2 * D * D + k * D + j]) * wc;
            sW1 += Wneigh2[D * D + k * D + j] * wc;
            sW2 += Wneigh2[2 * D * D + k * D + j] * wc;
        }
        g_Wsc[k * 2 + o] = sWs;
        g_Wn1c[k * 2 + o] = sW1;
        g_Wn2c[k * 2 + o] = sW2;
    }
    if (t < 2) {
        float s = bc[t];
        for (int j = 0; j < D; j++) s += (b2[D + j] + b2[2 * D + j]) * Wc[j * 2 + t];
        g_bc2[t] = s;
    }
}

// ---------------- transpose + bf16-split layer-1 weights (once) ----------------
__global__ void wsplit_kernel(const float* __restrict__ Wself1,
                              const float* __restrict__ Wneigh1) {
    int m = blockIdx.x >> 5;    // 0..4
    int part = blockIdx.x & 31;
    int f = part * 512 + threadIdx.x * 2;
    int n = f >> 7, k = f & 127;  // k even
    float w0, w1;
    if (m == 2) {
        w0 = Wself1[D * D + k * D + n] + Wself1[2 * D * D + k * D + n];
        w1 = Wself1[D * D + (k + 1) * D + n] + Wself1[2 * D * D + (k + 1) * D + n];
    } else {
        const float* src = (m == 0) ? Wself1
                         : (m == 1) ? Wneigh1
                         : (m == 3) ? (Wneigh1 + D * D) : (Wneigh1 + 2 * D * D);
        w0 = src[k * D + n];
        w1 = src[(k + 1) * D + n];
    }
    unsigned hi, lo;
    split2(w0, w1, hi, lo);
    *(unsigned*)&g_Whi[m * 16384 + n * 128 + k] = hi;
    *(unsigned*)&g_Wlo[m * 16384 + n * 128 + k] = lo;
}

// ---------------- layer-1 edge scatter: s[dst] += ew * hsrc[src]; deg[dst] += 1 -----------
__global__ __launch_bounds__(256) void scatter_kernel(
    const float* __restrict__ hsrc, const int* __restrict__ src,
    const int* __restrict__ dst, const float* __restrict__ ew,
    float* __restrict__ s, float* __restrict__ deg) {
    int gt = blockIdx.x * 256 + threadIdx.x;
    int e = gt >> 5;
    if (e >= NEDGE) return;
    int lane = gt & 31;
    int sR = __ldg(src + e);
    int dR = __ldg(dst + e);
    float w = __ldg(ew + e);
    float4 v = __ldg((const float4*)(hsrc + (size_t)sR * D) + lane);
    v.x *= w; v.y *= w; v.z *= w; v.w *= w;
    float* p = s + (size_t)dR * D + lane * 4;
    asm volatile("red.global.add.v4.f32 [%0], {%1,%2,%3,%4};"
                 :: "l"(p), "f"(v.x), "f"(v.y), "f"(v.z), "f"(v.w) : "memory");
    if (deg != nullptr && lane == 0) atomicAdd(deg + dR, 1.0f);
}

// ---------------- layer-2 edge scatter on PROJECTED (2-dim) values ----------------
__global__ __launch_bounds__(256) void scatter2_kernel(
    const float* __restrict__ srcP, int off, const int* __restrict__ src,
    const int* __restrict__ dst, const float* __restrict__ ew, float* __restrict__ acc) {
    int e = blockIdx.x * 256 + threadIdx.x;
    if (e >= NEDGE) return;
    int sR = __ldg(src + e);
    int dR = __ldg(dst + e);
    float w = __ldg(ew + e);
    float2 v = *(const float2*)(srcP + (size_t)sR * 4 + off);
    v.x *= w; v.y *= w;
    float* p = acc + (size_t)dR * 2;
    asm volatile("red.global.add.v2.f32 [%0], {%1,%2};"
                 :: "l"(p), "f"(v.x), "f"(v.y) : "memory");
}

// ---------------- inv degree ----------------
__global__ void invdeg_kernel() {
    int i = blockIdx.x * 256 + threadIdx.x;
    if (i < NAPP) {
        g_inv1[i] = 1.0f / fmaxf(g_deg1[i], 1.0f);
        g_inv2[i] = 1.0f / fmaxf(g_deg2[i], 1.0f);
        if (i < NATTR) g_inv0[i] = 1.0f / fmaxf(g_deg0[i], 1.0f);
    }
}

// ---------------- mma helpers ----------------
__device__ __forceinline__ unsigned sptr(const void* p) {
    return (unsigned)__cvta_generic_to_shared(p);
}
__device__ __forceinline__ void cp16(void* dst, const void* src) {
    asm volatile("cp.async.ca.shared.global [%0], [%1], 16;"
                 :: "r"(sptr(dst)), "l"(src) : "memory");
}
#define CP_COMMIT() asm volatile("cp.async.commit_group;" ::: "memory")
#define CP_WAIT0() asm volatile("cp.async.wait_group 0;" ::: "memory")
#define LDSM4(R0, R1, R2, R3, ADDR)                                              \
    asm volatile("ldmatrix.sync.aligned.m8n8.x4.shared.b16 {%0,%1,%2,%3},[%4];"  \
                 : "=r"(R0), "=r"(R1), "=r"(R2), "=r"(R3) : "r"(ADDR))
__device__ __forceinline__ void mma16816(float* d, const unsigned* a, const unsigned* b) {
    asm volatile(
        "mma.sync.aligned.m16n8k16.row.col.f32.bf16.bf16.f32 "
        "{%0,%1,%2,%3}, {%4,%5,%6,%7}, {%8,%9}, {%0,%1,%2,%3};"
        : "+f"(d[0]), "+f"(d[1]), "+f"(d[2]), "+f"(d[3])
        : "r"(a[0]), "r"(a[1]), "r"(a[2]), "r"(a[3]), "r"(b[0]), "r"(b[1]));
}

// ---------------- tensor-core GEMM + fused projection epilogue -----------------------
// Computes h = relu( sum_j (A_j*scale_j) @ Wj + bias ) in registers, then accumulates
// outP[row][0:2] += h @ P0 and outP[row][2:4] += h @ P1 via red.v4 — the full 128-wide
// h is NEVER written to global.
#define SK 40  // 80B row stride: 16B-aligned, conflict-free ldmatrix phases
__global__ __launch_bounds__(256) void gemm_mma_kernel(
    const float* __restrict__ A0, const float* __restrict__ I0,
    const float* __restrict__ A1, const float* __restrict__ I1,
    const float* __restrict__ A2, const float* __restrict__ I2,
    const unsigned short* __restrict__ Wh0, const unsigned short* __restrict__ Wh1,
    const unsigned short* __restrict__ Wh2,
    const unsigned short* __restrict__ Wl0, const unsigned short* __restrict__ Wl1,
    const unsigned short* __restrict__ Wl2,
    const float* __restrict__ bias, const float* __restrict__ P0,
    const float* __restrict__ P1, float* __restrict__ outP, int M, int nin) {
    __shared__ __align__(16) unsigned short Ah[128 * SK];
    __shared__ __align__(16) unsigned short Al[128 * SK];
    __shared__ __align__(16) unsigned short Wh[128 * SK];
    __shared__ __align__(16) unsigned short Wl[128 * SK];
    __shared__ __align__(16) float Ps[128][4];
    const int t = threadIdx.x;
    const int lane = t & 31, wid = t >> 5;
    const int wm = wid & 3, wn = wid >> 2;
    const int row0 = blockIdx.x * 128;

    // projection matrices to smem (done once; first in-loop __syncthreads covers it)
    if (t < 128) {
        Ps[t][0] = P0[t * 2];
        Ps[t][1] = P0[t * 2 + 1];
        Ps[t][2] = P1 ? P1[t * 2] : 0.f;
        Ps[t][3] = P1 ? P1[t * 2 + 1] : 0.f;
    }

    float d[2][8][4];
#pragma unroll
    for (int i = 0; i < 2; i++)
#pragma unroll
        for (int j = 0; j < 8; j++)
#pragma unroll
            for (int q = 0; q < 4; q++) d[i][j][q] = 0.f;

    const int sel = lane >> 3, lr = lane & 7;
    const int a_row = (sel & 1) * 8 + lr;
    const int a_koff = (sel >> 1) * 8;
    const int b_col = (sel >> 1) * 8 + lr;
    const int b_koff = (sel & 1) * 8;

    const float* Aj[3] = {A0, A1, A2};
    const float* Ij[3] = {I0, I1, I2};
    const unsigned short* Whj[3] = {Wh0, Wh1, Wh2};
    const unsigned short* Wlj[3] = {Wl0, Wl1, Wl2};

    float4 va[4];
    auto loadA = [&](int it) {
        int jj = it >> 2, kc = it & 3, k0 = kc * 32;
        const float* A = Aj[jj];
        const float* I = Ij[jj];
#pragma unroll
        for (int i = 0; i < 4; i++) {
            int f = i * 256 + t;
            int r = f >> 3;
            int kq = f & 7;
            int grow = row0 + r;
            float4 v = make_float4(0.f, 0.f, 0.f, 0.f);
            if (grow < M) {
                v = *(const float4*)(A + (size_t)grow * 128 + k0 + kq * 4);
                if (I) { float sc = I[grow]; v.x *= sc; v.y *= sc; v.z *= sc; v.w *= sc; }
            }
            va[i] = v;
        }
    };

    const int total = nin * 4;
    loadA(0);
    for (int it = 0; it < total; it++) {
        int jj = it >> 2, kc = it & 3, k0 = kc * 32;
        __syncthreads();  // previous MMA done reading smem
#pragma unroll
        for (int i = 0; i < 4; i++) {
            int f = i * 256 + t;
            int r = f >> 3;
            int kq = f & 7;
            unsigned h01, l01, h23, l23;
            split2(va[i].x, va[i].y, h01, l01);
            split2(va[i].z, va[i].w, h23, l23);
            *(uint2*)&Ah[r * SK + kq * 4] = make_uint2(h01, h23);
            *(uint2*)&Al[r * SK + kq * 4] = make_uint2(l01, l23);
        }
        const unsigned short* WhG = Whj[jj];
        const unsigned short* WlG = Wlj[jj];
#pragma unroll
        for (int i = 0; i < 2; i++) {
            int f = i * 256 + t;
            int n = f >> 2;
            int q = f & 3;
            cp16(&Wh[n * SK + q * 8], WhG + n * 128 + k0 + q * 8);
            cp16(&Wl[n * SK + q * 8], WlG + n * 128 + k0 + q * 8);
        }
        CP_COMMIT();
        if (it + 1 < total) loadA(it + 1);
        CP_WAIT0();
        __syncthreads();
#pragma unroll
        for (int ks = 0; ks < 32; ks += 16) {
            unsigned ah[2][4], al[2][4], bh[8][2], bl[8][2];
#pragma unroll
            for (int mt = 0; mt < 2; mt++) {
                unsigned addr = sptr(&Ah[(wm * 32 + mt * 16 + a_row) * SK + ks + a_koff]);
                LDSM4(ah[mt][0], ah[mt][1], ah[mt][2], ah[mt][3], addr);
                addr = sptr(&Al[(wm * 32 + mt * 16 + a_row) * SK + ks + a_koff]);
                LDSM4(al[mt][0], al[mt][1], al[mt][2], al[mt][3], addr);
            }
#pragma unroll
            for (int bt = 0; bt < 4; bt++) {
                unsigned addr = sptr(&Wh[(wn * 64 + bt * 16 + b_col) * SK + ks + b_koff]);
                LDSM4(bh[2 * bt][0], bh[2 * bt][1], bh[2 * bt + 1][0], bh[2 * bt + 1][1], addr);
                addr = sptr(&Wl[(wn * 64 + bt * 16 + b_col) * SK + ks + b_koff]);
                LDSM4(bl[2 * bt][0], bl[2 * bt][1], bl[2 * bt + 1][0], bl[2 * bt + 1][1], addr);
            }
#pragma unroll
            for (int mt = 0; mt < 2; mt++)
#pragma unroll
                for (int nt = 0; nt < 8; nt++) {
                    mma16816(d[mt][nt], ah[mt], bh[nt]);  // hi*hi
                    mma16816(d[mt][nt], ah[mt], bl[nt]);  // hi*lo
                    mma16816(d[mt][nt], al[mt], bh[nt]);  // lo*hi
                }
        }
    }
    // ---- epilogue: bias + relu + 4-wide projection + red.v4 per row ----
    const int tig = lane & 3, grp = lane >> 2;
    float pr[4][4];  // [row slot: mt*2 + (0:r, 1:r+8)][proj 0..3]
#pragma unroll
    for (int i = 0; i < 4; i++)
#pragma unroll
        for (int q = 0; q < 4; q++) pr[i][q] = 0.f;
#pragma unroll
    for (int nt = 0; nt < 8; nt++) {
        int col = wn * 64 + nt * 8 + tig * 2;
        float b0 = bias[col], b1 = bias[col + 1];
        float4 p0 = *(const float4*)&Ps[col][0];
        float4 p1 = *(const float4*)&Ps[col + 1][0];
#pragma unroll
        for (int mt = 0; mt < 2; mt++) {
            float v0 = fmaxf(d[mt][nt][0] + b0, 0.f);
            float v1 = fmaxf(d[mt][nt][1] + b1, 0.f);
            float v2 = fmaxf(d[mt][nt][2] + b0, 0.f);
            float v3 = fmaxf(d[mt][nt][3] + b1, 0.f);
            int a = mt * 2, b = mt * 2 + 1;
            pr[a][0] += v0 * p0.x + v1 * p1.x;
            pr[a][1] += v0 * p0.y + v1 * p1.y;
            pr[a][2] += v0 * p0.z + v1 * p1.z;
            pr[a][3] += v0 * p0.w + v1 * p1.w;
            pr[b][0] += v2 * p0.x + v3 * p1.x;
            pr[b][1] += v2 * p0.y + v3 * p1.y;
            pr[b][2] += v2 * p0.z + v3 * p1.z;
            pr[b][3] += v2 * p0.w + v3 * p1.w;
        }
    }
#pragma unroll
    for (int mt = 0; mt < 2; mt++) {
        int r = row0 + wm * 32 + mt * 16 + grp;
        if (r < M) {
            float* p = outP + (size_t)r * 4;
            asm volatile("red.global.add.v4.f32 [%0], {%1,%2,%3,%4};"
                         :: "l"(p), "f"(pr[mt * 2][0]), "f"(pr[mt * 2][1]),
                            "f"(pr[mt * 2][2]), "f"(pr[mt * 2][3]) : "memory");
        }
        if (r + 8 < M) {
            float* p = outP + (size_t)(r + 8) * 4;
            asm volatile("red.global.add.v4.f32 [%0], {%1,%2,%3,%4};"
                         :: "l"(p), "f"(pr[mt * 2 + 1][0]), "f"(pr[mt * 2 + 1][1]),
                            "f"(pr[mt * 2 + 1][2]), "f"(pr[mt * 2 + 1][3]) : "memory");
        }
    }
}

// ---------------- final: out[i] = happP_self + acc1/deg1 + acc2/deg2 + bc2 ----------------
__global__ __launch_bounds__(256) void final2_kernel(float* __restrict__ out) {
    int i = blockIdx.x * 256 + threadIdx.x;
    if (i >= NAPP) return;
    float i1 = g_inv1[i], i2 = g_inv2[i];
    float4 hp = *(const float4*)(g_happP + (size_t)i * 4);
    float2 a1 = *(const float2*)(g_acc1 + (size_t)i * 2);
    float2 a2 = *(const float2*)(g_acc2 + (size_t)i * 2);
    out[2 * i + 0] = hp.x + a1.x * i1 + a2.x * i2 + g_bc2[0];
    out[2 * i + 1] = hp.y + a1.y * i1 + a2.y * i2 + g_bc2[1];
}

extern "C" void kernel_launch(void* const* d_in, const int* in_sizes, int n_in,
                              void* d_out, int out_size) {
    const float* x_app = (const float*)d_in[0];
    const float* x_attr = (const float*)d_in[1];
    const float* ew0 = (const float*)d_in[2];
    const float* ew1 = (const float*)d_in[3];
    const float* ew2 = (const float*)d_in[4];
    const float* Wself1 = (const float*)d_in[5];
    const float* Wneigh1 = (const float*)d_in[6];
    const float* b1 = (const float*)d_in[7];
    const float* Wself2 = (const float*)d_in[8];
    const float* Wneigh2 = (const float*)d_in[9];
    const float* b2 = (const float*)d_in[10];
    const float* Wc = (const float*)d_in[11];
    const float* bc = (const float*)d_in[12];
    const int* src0 = (const int*)d_in[13];
    const int* dst0 = (const int*)d_in[14];
    const int* src1 = (const int*)d_in[15];
    const int* dst1 = (const int*)d_in[16];
    const int* src2 = (const int*)d_in[17];
    const int* dst2 = (const int*)d_in[18];
    float* out = (float*)d_out;

    float *s0, *s1, *s2, *deg0, *deg1, *deg2;
    float *inv0, *inv1, *inv2, *hattrP, *happP, *acc1, *acc2, *bapp;
    float *wsc, *wn1c, *wn2c;
    unsigned short *whi, *wlo;
    cudaGetSymbolAddress((void**)&s0, g_s0);
    cudaGetSymbolAddress((void**)&s1, g_s1);
    cudaGetSymbolAddress((void**)&s2, g_s2);
    cudaGetSymbolAddress((void**)&deg0, g_deg0);
    cudaGetSymbolAddress((void**)&deg1, g_deg1);
    cudaGetSymbolAddress((void**)&deg2, g_deg2);
    cudaGetSymbolAddress((void**)&inv0, g_inv0);
    cudaGetSymbolAddress((void**)&inv1, g_inv1);
    cudaGetSymbolAddress((void**)&inv2, g_inv2);
    cudaGetSymbolAddress((void**)&hattrP, g_hattrP);
    cudaGetSymbolAddress((void**)&happP, g_happP);
    cudaGetSymbolAddress((void**)&acc1, g_acc1);
    cudaGetSymbolAddress((void**)&acc2, g_acc2);
    cudaGetSymbolAddress((void**)&bapp, g_bapp);
    cudaGetSymbolAddress((void**)&wsc, g_Wsc);
    cudaGetSymbolAddress((void**)&wn1c, g_Wn1c);
    cudaGetSymbolAddress((void**)&wn2c, g_Wn2c);
    cudaGetSymbolAddress((void**)&whi, g_Whi);
    cudaGetSymbolAddress((void**)&wlo, g_Wlo);

    zero_kernel<<<2048, 256>>>();
    prep_kernel<<<1, 256>>>(b1, Wself2, Wneigh2, b2, Wc, bc);
    wsplit_kernel<<<160, 256>>>(Wself1, Wneigh1);

    const int SCATTER_BLOCKS = (NEDGE * 32) / 256;  // 62500
    // layer 1 aggregations (full 128-wide)
    scatter_kernel<<<SCATTER_BLOCKS, 256>>>(x_app, src0, dst0, ew0, s0, deg0);
    scatter_kernel<<<SCATTER_BLOCKS, 256>>>(x_attr, src1, dst1, ew1, s1, deg1);
    scatter_kernel<<<SCATTER_BLOCKS, 256>>>(x_app, src2, dst2, ew2, s2, deg2);
    invdeg_kernel<<<(NAPP + 255) / 256, 256>>>();

    const int MATSZ = 128 * 128;
    // layer-1 GEMMs with fused layer-2 projection epilogue (hidden states never stored)
    gemm_mma_kernel<<<(NATTR + 127) / 128, 256>>>(
        x_attr, nullptr, s0, inv0, nullptr, nullptr,
        whi + 0 * MATSZ, whi + 1 * MATSZ, nullptr,
        wlo + 0 * MATSZ, wlo + 1 * MATSZ, nullptr,
        b1, wn1c, nullptr, hattrP, NATTR, 2);
    gemm_mma_kernel<<<(NAPP + 127) / 128, 256>>>(
        x_app, nullptr, s1, inv1, s2, inv2,
        whi + 2 * MATSZ, whi + 3 * MATSZ, whi + 4 * MATSZ,
        wlo + 2 * MATSZ, wlo + 3 * MATSZ, wlo + 4 * MATSZ,
        bapp, wsc, wn2c, happP, NAPP, 3);

    // layer-2 aggregations on 2-dim projected values (rel0 output unused -> skipped)
    const int S2_BLOCKS = (NEDGE + 255) / 256;
    scatter2_kernel<<<S2_BLOCKS, 256>>>(hattrP, 0, src1, dst1, ew1, acc1);
    scatter2_kernel<<<S2_BLOCKS, 256>>>(happP, 2, src2, dst2, ew2, acc2);

    final2_kernel<<<(NAPP + 255) / 256, 256>>>(out);
}